// round 7
// baseline (speedup 1.0000x reference)
#include <cuda_runtime.h>
#include <cuda_bf16.h>
#include <cuda_fp16.h>
#include <cstdint>

// ---------------------------------------------------------------------------
// RelationLayer: L=128, B=16, E=512, C=64, KERNELS={1,3,5,7}, M=256, OUT=256
//  1) prep: split x -> bf16 hi/lo, repack conv weights, pack Wuv  (1 launch)
//  2) G = x(2048x512) @ Wr               (bf16 3-term GEMM, 128x128 tiles)
//  3) f = lrelu(gather taps + bias) -> bf16 hi/lo planes
//  4) uv = f(2048x256) @ Wuv(256x128)    (bf16 3-term GEMM, 64x64 tiles)
//  5) pair kernel: mma.sync m16n8k16 fp16, activations single-fp16,
//     weights fp16 hi/lo (2-term), in-register layer chaining, fused head.
// ---------------------------------------------------------------------------

#define LL 128
#define BB 16
#define EE 512
#define MM 256
#define ROWS 2048
#define GCOLS 1024

#define NX (ROWS * EE)
#define NW (EE * GCOLS)
#define NU (128 * MM)
#define NF (ROWS * MM)

__device__ float g_G[ROWS * GCOLS];
__device__ float g_uv[ROWS * 128];
__device__ __nv_bfloat16 g_xh[NX];
__device__ __nv_bfloat16 g_xl[NX];
__device__ __nv_bfloat16 g_fh[NF];
__device__ __nv_bfloat16 g_fl[NF];
__device__ __nv_bfloat16 g_Wrh[NW];
__device__ __nv_bfloat16 g_Wrl[NW];
__device__ __nv_bfloat16 g_Wuvh[NU];
__device__ __nv_bfloat16 g_Wuvl[NU];

// ===================== helpers ==============================================
__device__ __forceinline__ float lrelu(float x) { return fmaxf(x, 0.1f * x); }

__device__ __forceinline__ void split1(float v, __nv_bfloat16& h, __nv_bfloat16& l) {
    h = __float2bfloat16(v);
    l = __float2bfloat16(v - __bfloat162float(h));
}

// pack two f32 into one fp16x2 word (low 16 bits = first element)
__device__ __forceinline__ uint32_t packh2(float a, float b) {
    __half2 h = __floats2half2_rn(a, b);
    return *(uint32_t*)&h;
}
// split two f32 into fp16-hi word and fp16-lo (residual) word
__device__ __forceinline__ void splith2(float a, float b,
                                        uint32_t& hi, uint32_t& lo) {
    __half ha = __float2half_rn(a), hb = __float2half_rn(b);
    __half la = __float2half_rn(a - __half2float(ha));
    __half lb = __float2half_rn(b - __half2float(hb));
    __half2 hp = __halves2half2(ha, hb);
    __half2 lp = __halves2half2(la, lb);
    hi = *(uint32_t*)&hp;
    lo = *(uint32_t*)&lp;
}

// mma.sync m16n8k16 bf16 -> f32 accumulate (baseline PTX)
__device__ __forceinline__ void mma16816(float c[4], const uint32_t a[4],
                                         uint32_t b0, uint32_t b1) {
    asm volatile(
        "mma.sync.aligned.m16n8k16.row.col.f32.bf16.bf16.f32 "
        "{%0,%1,%2,%3}, {%4,%5,%6,%7}, {%8,%9}, {%0,%1,%2,%3};"
        : "+f"(c[0]), "+f"(c[1]), "+f"(c[2]), "+f"(c[3])
        : "r"(a[0]), "r"(a[1]), "r"(a[2]), "r"(a[3]), "r"(b0), "r"(b1));
}
// mma.sync m16n8k16 fp16 -> f32 accumulate (baseline PTX)
__device__ __forceinline__ void mmah(float c[4], const uint32_t a[4],
                                     uint32_t b0, uint32_t b1) {
    asm volatile(
        "mma.sync.aligned.m16n8k16.row.col.f32.f16.f16.f32 "
        "{%0,%1,%2,%3}, {%4,%5,%6,%7}, {%8,%9}, {%0,%1,%2,%3};"
        : "+f"(c[0]), "+f"(c[1]), "+f"(c[2]), "+f"(c[3])
        : "r"(a[0]), "r"(a[1]), "r"(a[2]), "r"(a[3]), "r"(b0), "r"(b1));
}

// ===================== prep: splitx + repack_wr + pack_wuv ==================
__global__ void prep_kernel(const float* __restrict__ x,
                            const float* __restrict__ cw0,
                            const float* __restrict__ cw1,
                            const float* __restrict__ cw2,
                            const float* __restrict__ cw3,
                            const float* __restrict__ mw0) {
    int idx = blockIdx.x * 256 + threadIdx.x;
    if (idx < NX) {
        split1(x[idx], g_xh[idx], g_xl[idx]);
    } else if (idx < NX + NW) {
        int j = idx - NX;
        int col = j >> 9;            // n: 0..1023
        int e = j & 511;             // k
        int p = col >> 6;
        int c = col & 63;
        const float* w; int k, t;
        if (p < 1)      { w = cw0; k = 1; t = p; }
        else if (p < 4) { w = cw1; k = 3; t = p - 1; }
        else if (p < 9) { w = cw2; k = 5; t = p - 4; }
        else            { w = cw3; k = 7; t = p - 9; }
        split1(w[(c * k + t) * EE + e], g_Wrh[j], g_Wrl[j]);
    } else if (idx < NX + NW + NU) {
        int j = idx - NX - NW;
        int n = j >> 8;              // 0..127
        int k = j & 255;
        float v;
        if (n < 64) v = mw0[n * 512 + k];
        else        v = mw0[(n - 64) * 512 + 256 + k];
        split1(v, g_Wuvh[j], g_Wuvl[j]);
    }
}

// ===================== tensor-core bf16-split GEMM (templated tile) ========
// C(MxN) = A(MxK) @ B(KxN), A and B given as bf16 hi/lo planes [rows][K].
// Tile T x T, K-step 64, 256 threads (8 warps, 4 along m x 2 along n).
// M%T==0, N%T==0, K%64==0. T in {64, 128}.
#define TSG 72            // padded k-stride in bf16 units

template <int T>
__global__ void __launch_bounds__(256, 1)
gemm_bf_kernel(const __nv_bfloat16* __restrict__ Ahig,
               const __nv_bfloat16* __restrict__ Alog,
               const __nv_bfloat16* __restrict__ Bhig,
               const __nv_bfloat16* __restrict__ Blog,
               float* __restrict__ C, int M, int N, int K) {
    constexpr int SAH = 0;
    constexpr int SAL = T * TSG;
    constexpr int SBH = 2 * T * TSG;
    constexpr int SBL = 3 * T * TSG;
    constexpr int MT = T / 64;       // m16x2 tiles per warp
    constexpr int NT = T / 16;       // n8 tiles per warp
    constexpr int IT = T / 32;       // loader iterations per plane

    extern __shared__ __nv_bfloat16 sm[];
    int tid = threadIdx.x, w = tid >> 5, lane = tid & 31;
    int g = lane >> 2, t4 = lane & 3;
    int m0 = blockIdx.y * T, n0 = blockIdx.x * T;
    int mw = (w & 3) * (T / 4);
    int nw = (w >> 2) * (T / 2);

    float Cc[MT][NT][4];
#pragma unroll
    for (int mt = 0; mt < MT; mt++)
#pragma unroll
        for (int nt = 0; nt < NT; nt++)
#pragma unroll
            for (int q = 0; q < 4; q++) Cc[mt][nt][q] = 0.f;

    for (int k0 = 0; k0 < K; k0 += 64) {
        uint4 ah[IT], al[IT], bh[IT], bl[IT];
#pragma unroll
        for (int it = 0; it < IT; it++) {
            int u = tid + it * 256;
            int row = u >> 3;
            int kq = (u & 7) * 8;
            ah[it] = *(const uint4*)(Ahig + (m0 + row) * K + k0 + kq);
            al[it] = *(const uint4*)(Alog + (m0 + row) * K + k0 + kq);
            bh[it] = *(const uint4*)(Bhig + (n0 + row) * K + k0 + kq);
            bl[it] = *(const uint4*)(Blog + (n0 + row) * K + k0 + kq);
        }
        __syncthreads();
#pragma unroll
        for (int it = 0; it < IT; it++) {
            int u = tid + it * 256;
            int row = u >> 3;
            int kq = (u & 7) * 8;
            int base = row * TSG + kq;
            *(uint4*)&sm[SAH + base] = ah[it];
            *(uint4*)&sm[SAL + base] = al[it];
            *(uint4*)&sm[SBH + base] = bh[it];
            *(uint4*)&sm[SBL + base] = bl[it];
        }
        __syncthreads();

#pragma unroll
        for (int kc = 0; kc < 4; kc++) {
            int kk = kc * 16 + 2 * t4;
            uint32_t Ahi[MT][4], Alo[MT][4];
#pragma unroll
            for (int mt = 0; mt < MT; mt++) {
                int r0 = mw + mt * 16 + g;
                int r1 = r0 + 8;
                Ahi[mt][0] = *(const uint32_t*)&sm[SAH + r0 * TSG + kk];
                Ahi[mt][1] = *(const uint32_t*)&sm[SAH + r1 * TSG + kk];
                Ahi[mt][2] = *(const uint32_t*)&sm[SAH + r0 * TSG + kk + 8];
                Ahi[mt][3] = *(const uint32_t*)&sm[SAH + r1 * TSG + kk + 8];
                Alo[mt][0] = *(const uint32_t*)&sm[SAL + r0 * TSG + kk];
                Alo[mt][1] = *(const uint32_t*)&sm[SAL + r1 * TSG + kk];
                Alo[mt][2] = *(const uint32_t*)&sm[SAL + r0 * TSG + kk + 8];
                Alo[mt][3] = *(const uint32_t*)&sm[SAL + r1 * TSG + kk + 8];
            }
#pragma unroll
            for (int nt = 0; nt < NT; nt++) {
                int nrow = nw + nt * 8 + g;
                uint32_t bh0 = *(const uint32_t*)&sm[SBH + nrow * TSG + kk];
                uint32_t bh1 = *(const uint32_t*)&sm[SBH + nrow * TSG + kk + 8];
                uint32_t bl0 = *(const uint32_t*)&sm[SBL + nrow * TSG + kk];
                uint32_t bl1 = *(const uint32_t*)&sm[SBL + nrow * TSG + kk + 8];
#pragma unroll
                for (int mt = 0; mt < MT; mt++) {
                    mma16816(Cc[mt][nt], Ahi[mt], bh0, bh1);
                    mma16816(Cc[mt][nt], Ahi[mt], bl0, bl1);
                    mma16816(Cc[mt][nt], Alo[mt], bh0, bh1);
                }
            }
        }
    }

    // epilogue: write f32
#pragma unroll
    for (int mt = 0; mt < MT; mt++) {
        int r0 = m0 + mw + mt * 16 + g;
        int r1 = r0 + 8;
#pragma unroll
        for (int nt = 0; nt < NT; nt++) {
            int col = n0 + nw + nt * 8 + 2 * t4;
            *(float2*)(C + r0 * N + col) = make_float2(Cc[mt][nt][0], Cc[mt][nt][1]);
            *(float2*)(C + r1 * N + col) = make_float2(Cc[mt][nt][2], Cc[mt][nt][3]);
        }
    }
}

#define GEMM_SMEM_BYTES_128 (4 * 128 * TSG * 2)
#define GEMM_SMEM_BYTES_64  (4 * 64 * TSG * 2)

// ===================== gather taps -> f (bf16 hi/lo, ILP 8) =================
__global__ void gather_f_kernel(const float* __restrict__ cb0,
                                const float* __restrict__ cb1,
                                const float* __restrict__ cb2,
                                const float* __restrict__ cb3) {
    int t0 = blockIdx.x * 256 + threadIdx.x;   // 0..65535
#pragma unroll
    for (int q = 0; q < 8; q++) {
        int idx = t0 + q * 65536;
        int row = idx >> 8;        // (l,b): 0..2047
        int m = idx & 255;
        int l = row >> 4, b = row & 15;
        int br = m >> 6, c = m & 63;
        int k, pad, base;
        const float* cb;
        if (br == 0)      { k = 1; base = 0; cb = cb0; }
        else if (br == 1) { k = 3; base = 1; cb = cb1; }
        else if (br == 2) { k = 5; base = 4; cb = cb2; }
        else              { k = 7; base = 9; cb = cb3; }
        pad = (k - 1) >> 1;
        float sum = cb[c];
        for (int tt = 0; tt < k; tt++) {
            int l2 = l - pad + tt;
            if ((unsigned)l2 < (unsigned)LL)
                sum += g_G[(l2 * BB + b) * GCOLS + (base + tt) * 64 + c];
        }
        split1(lrelu(sum), g_fh[idx], g_fl[idx]);
    }
}

// ===================== pair kernel (mma.sync fp16 2-term) ===================
// grid (16, 16): blockIdx.x -> j-tile of 8, blockIdx.y -> b. 128 threads.
// Warp w handles i-rows [w*32, w*32+32) as 2 m-tiles of 16.
// Weights staged as packed uint4 fragments (fp16 hi/lo):
//   W4[l][kc][n][t4] = {wh_b0, wh_b1, wl_b0, wl_b1} (16B per entry)
// Activations: single fp16 fragments (D = A*Wh + A*Wl per tile -> 4 mma).
#define PV_STRIDE 132
#define P_W4   0
#define P_V    49152
#define P_U    82944
#define P_B    84992
#define P_RED  86016
#define P_SR   94208
#define P_TR   96256
#define PAIR_SMEM_BYTES 98304

__global__ void __launch_bounds__(128, 2)
pair_mma_kernel(const float* __restrict__ uv,
                const float* __restrict__ mw1, const float* __restrict__ mw2,
                const float* __restrict__ mw3,
                const float* __restrict__ mb0, const float* __restrict__ mb1,
                const float* __restrict__ mb2, const float* __restrict__ mb3,
                const float* __restrict__ lw0, const float* __restrict__ lb0,
                const float* __restrict__ lw1, const float* __restrict__ lb1,
                float* __restrict__ out) {
    extern __shared__ char smp[];
    int tid = threadIdx.x, w = tid >> 5, lane = tid & 31;
    int g = lane >> 2, t4 = lane & 3;
    int b = blockIdx.y, j0 = blockIdx.x * 8;

    // ---- stage weights as packed uint4 fragments (fp16 hi/lo) ----
    {
        uint4* W4 = (uint4*)(smp + P_W4);
        for (int e = tid; e < 3072; e += 128) {
            int t4i = e & 3;
            int n = (e >> 2) & 63;
            int kc = (e >> 8) & 3;
            int l = e >> 10;
            const float* wsrc = (l == 0) ? mw1 : (l == 1) ? mw2 : mw3;
            int k0 = kc * 16 + 2 * t4i;
            float2 v01 = *(const float2*)(wsrc + n * 64 + k0);
            float2 v89 = *(const float2*)(wsrc + n * 64 + k0 + 8);
            uint32_t h0, l0, h1, l1;
            splith2(v01.x, v01.y, h0, l0);
            splith2(v89.x, v89.y, h1, l1);
            uint4 pk; pk.x = h0; pk.y = h1; pk.z = l0; pk.w = l1;
            W4[e] = pk;
        }
    }
    // ---- stage V[k][i] (f32, stride 132) ----
    {
        float* V = (float*)(smp + P_V);
        const float* vp = uv + (tid * BB + b) * 128 + 64;
#pragma unroll
        for (int q = 0; q < 16; q++) {
            float4 v4 = *(const float4*)(vp + q * 4);
            V[(q * 4 + 0) * PV_STRIDE + tid] = v4.x;
            V[(q * 4 + 1) * PV_STRIDE + tid] = v4.y;
            V[(q * 4 + 2) * PV_STRIDE + tid] = v4.z;
            V[(q * 4 + 3) * PV_STRIDE + tid] = v4.w;
        }
    }
    if (tid < 64) {
        float* U = (float*)(smp + P_U);
#pragma unroll
        for (int jt = 0; jt < 8; jt++)
            U[jt * 64 + tid] = uv[((j0 + jt) * BB + b) * 128 + tid];
        float* Bs = (float*)(smp + P_B);
        Bs[tid] = mb0[tid];
        Bs[64 + tid] = mb1[tid];
        Bs[128 + tid] = mb2[tid];
        Bs[192 + tid] = mb3[tid];
    }
    __syncthreads();

    const float* V = (const float*)(smp + P_V);
    const float* U = (const float*)(smp + P_U);
    const float* BIAS = (const float*)(smp + P_B);
    const uint4* W4 = (const uint4*)(smp + P_W4);
    float* RED = (float*)(smp + P_RED);
    float* SR = (float*)(smp + P_SR);

    for (int jt = 0; jt < 8; jt++) {
        uint32_t A[2][4][4];

        // ---- layer-1 A fragments: x = lrelu(u + v + b0), single fp16 ----
#pragma unroll
        for (int mt = 0; mt < 2; mt++) {
            int r0 = w * 32 + mt * 16 + g;
            int r1 = r0 + 8;
#pragma unroll
            for (int kc = 0; kc < 4; kc++) {
                int k0 = kc * 16 + 2 * t4;
                float ub0 = U[jt * 64 + k0]     + BIAS[k0];
                float ub1 = U[jt * 64 + k0 + 1] + BIAS[k0 + 1];
                float ub8 = U[jt * 64 + k0 + 8] + BIAS[k0 + 8];
                float ub9 = U[jt * 64 + k0 + 9] + BIAS[k0 + 9];
                float x00 = lrelu(ub0 + V[k0 * PV_STRIDE + r0]);
                float x01 = lrelu(ub1 + V[(k0 + 1) * PV_STRIDE + r0]);
                float x10 = lrelu(ub0 + V[k0 * PV_STRIDE + r1]);
                float x11 = lrelu(ub1 + V[(k0 + 1) * PV_STRIDE + r1]);
                float x08 = lrelu(ub8 + V[(k0 + 8) * PV_STRIDE + r0]);
                float x09 = lrelu(ub9 + V[(k0 + 9) * PV_STRIDE + r0]);
                float x18 = lrelu(ub8 + V[(k0 + 8) * PV_STRIDE + r1]);
                float x19 = lrelu(ub9 + V[(k0 + 9) * PV_STRIDE + r1]);
                A[mt][kc][0] = packh2(x00, x01);
                A[mt][kc][1] = packh2(x10, x11);
                A[mt][kc][2] = packh2(x08, x09);
                A[mt][kc][3] = packh2(x18, x19);
            }
        }

        // ---- 3 chained MMA layers (2-term: A*Wh + A*Wl) ----
        float Cc[2][8][4];
#pragma unroll
        for (int l = 0; l < 3; l++) {
#pragma unroll
            for (int mt = 0; mt < 2; mt++)
#pragma unroll
                for (int nt = 0; nt < 8; nt++)
#pragma unroll
                    for (int q = 0; q < 4; q++) Cc[mt][nt][q] = 0.f;

#pragma unroll
            for (int kc = 0; kc < 4; kc++) {
#pragma unroll
                for (int nt = 0; nt < 8; nt++) {
                    uint4 wq = W4[((l * 4 + kc) * 64 + nt * 8 + g) * 4 + t4];
                    mmah(Cc[0][nt], A[0][kc], wq.x, wq.y);
                    mmah(Cc[1][nt], A[1][kc], wq.x, wq.y);
                    mmah(Cc[0][nt], A[0][kc], wq.z, wq.w);
                    mmah(Cc[1][nt], A[1][kc], wq.z, wq.w);
                }
            }

            if (l < 2) {
                const float* bl = BIAS + 64 * (l + 1);
#pragma unroll
                for (int nt = 0; nt < 8; nt++) {
                    int col = nt * 8 + 2 * t4;
                    float bx = bl[col], by = bl[col + 1];
                    int kc2 = nt >> 1, ri = (nt & 1) * 2;
#pragma unroll
                    for (int mt = 0; mt < 2; mt++) {
                        float h0 = lrelu(Cc[mt][nt][0] + bx);
                        float h1 = lrelu(Cc[mt][nt][1] + by);
                        float h2 = lrelu(Cc[mt][nt][2] + bx);
                        float h3 = lrelu(Cc[mt][nt][3] + by);
                        A[mt][kc2][ri]     = packh2(h0, h1);
                        A[mt][kc2][ri + 1] = packh2(h2, h3);
                    }
                }
            }
        }

        // ---- final: bias + lrelu, reduce over i (no block sync needed) ----
        {
            const float* bl = BIAS + 192;
#pragma unroll
            for (int nt = 0; nt < 8; nt++) {
                int col = nt * 8 + 2 * t4;
                float bx = bl[col], by = bl[col + 1];
                float s0 = lrelu(Cc[0][nt][0] + bx) + lrelu(Cc[0][nt][2] + bx) +
                           lrelu(Cc[1][nt][0] + bx) + lrelu(Cc[1][nt][2] + bx);
                float s1 = lrelu(Cc[0][nt][1] + by) + lrelu(Cc[0][nt][3] + by) +
                           lrelu(Cc[1][nt][1] + by) + lrelu(Cc[1][nt][3] + by);
                s0 += __shfl_xor_sync(0xffffffffu, s0, 4);
                s0 += __shfl_xor_sync(0xffffffffu, s0, 8);
                s0 += __shfl_xor_sync(0xffffffffu, s0, 16);
                s1 += __shfl_xor_sync(0xffffffffu, s1, 4);
                s1 += __shfl_xor_sync(0xffffffffu, s1, 8);
                s1 += __shfl_xor_sync(0xffffffffu, s1, 16);
                if (lane < 4) {
                    RED[jt * 256 + w * 64 + col] = s0;
                    RED[jt * 256 + w * 64 + col + 1] = s1;
                }
            }
        }
    }
    __syncthreads();

    // cross-warp sum -> SR[jt][c]
#pragma unroll
    for (int q = 0; q < 4; q++) {
        int idx = tid + 128 * q;        // jt*64 + c
        int base = (idx >> 6) * 256 + (idx & 63);
        SR[idx] = RED[base] + RED[base + 64] + RED[base + 128] + RED[base + 192];
    }
    __syncthreads();

    // ---- fused head: t = lrelu(s@lw0.T+lb0); out = lrelu(t@lw1.T+lb1) ----
    float* TR = (float*)(smp + P_TR);
#pragma unroll
    for (int q = 0; q < 4; q++) {
        int idx = tid + 128 * q;
        int jt = idx >> 6, o = idx & 63;
        const float* wr = lw0 + o * 64;
        float acc = lb0[o];
#pragma unroll
        for (int c = 0; c < 64; c += 4) {
            float4 w4 = *(const float4*)(wr + c);
            acc += SR[jt * 64 + c] * w4.x + SR[jt * 64 + c + 1] * w4.y +
                   SR[jt * 64 + c + 2] * w4.z + SR[jt * 64 + c + 3] * w4.w;
        }
        TR[idx] = lrelu(acc);
    }
    __syncthreads();
#pragma unroll
    for (int q = 0; q < 16; q++) {
        int idx = tid + 128 * q;
        int jt = idx >> 8, o = idx & 255;
        const float* wr = lw1 + o * 64;
        float acc = lb1[o];
#pragma unroll
        for (int c = 0; c < 64; c += 4) {
            float4 w4 = *(const float4*)(wr + c);
            acc += TR[jt * 64 + c] * w4.x + TR[jt * 64 + c + 1] * w4.y +
                   TR[jt * 64 + c + 2] * w4.z + TR[jt * 64 + c + 3] * w4.w;
        }
        out[((j0 + jt) * BB + b) * 256 + o] = lrelu(acc);
    }
}

// ===================== host launch ==========================================
extern "C" void kernel_launch(void* const* d_in, const int* in_sizes, int n_in,
                              void* d_out, int out_size) {
    const float* x   = (const float*)d_in[0];
    const float* cw0 = (const float*)d_in[1];
    const float* cb0 = (const float*)d_in[2];
    const float* cw1 = (const float*)d_in[3];
    const float* cb1 = (const float*)d_in[4];
    const float* cw2 = (const float*)d_in[5];
    const float* cb2 = (const float*)d_in[6];
    const float* cw3 = (const float*)d_in[7];
    const float* cb3 = (const float*)d_in[8];
    const float* mw0 = (const float*)d_in[9];
    const float* mb0 = (const float*)d_in[10];
    const float* mw1 = (const float*)d_in[11];
    const float* mb1 = (const float*)d_in[12];
    const float* mw2 = (const float*)d_in[13];
    const float* mb2 = (const float*)d_in[14];
    const float* mw3 = (const float*)d_in[15];
    const float* mb3 = (const float*)d_in[16];
    const float* lw0 = (const float*)d_in[17];
    const float* lb0 = (const float*)d_in[18];
    const float* lw1 = (const float*)d_in[19];
    const float* lb1 = (const float*)d_in[20];
    float* out = (float*)d_out;

    float *G, *uvb;
    __nv_bfloat16 *xh, *xl, *fh, *fl, *Wrh, *Wrl, *Wuvh, *Wuvl;
    cudaGetSymbolAddress((void**)&G, g_G);
    cudaGetSymbolAddress((void**)&uvb, g_uv);
    cudaGetSymbolAddress((void**)&xh, g_xh);
    cudaGetSymbolAddress((void**)&xl, g_xl);
    cudaGetSymbolAddress((void**)&fh, g_fh);
    cudaGetSymbolAddress((void**)&fl, g_fl);
    cudaGetSymbolAddress((void**)&Wrh, g_Wrh);
    cudaGetSymbolAddress((void**)&Wrl, g_Wrl);
    cudaGetSymbolAddress((void**)&Wuvh, g_Wuvh);
    cudaGetSymbolAddress((void**)&Wuvl, g_Wuvl);

    // 1) prep (split x, repack conv weights, pack Wuv)
    prep_kernel<<<(NX + NW + NU + 255) / 256, 256>>>(x, cw0, cw1, cw2, cw3, mw0);

    cudaFuncSetAttribute(gemm_bf_kernel<128>,
                         cudaFuncAttributeMaxDynamicSharedMemorySize,
                         GEMM_SMEM_BYTES_128);
    cudaFuncSetAttribute(gemm_bf_kernel<64>,
                         cudaFuncAttributeMaxDynamicSharedMemorySize,
                         GEMM_SMEM_BYTES_64);

    // 2) conv as GEMM: G(2048x1024) = x(2048x512) @ Wr  (128x128 tiles)
    gemm_bf_kernel<128><<<dim3(GCOLS / 128, ROWS / 128), 256,
                          GEMM_SMEM_BYTES_128>>>(
        xh, xl, Wrh, Wrl, G, ROWS, GCOLS, EE);

    // 3) gather taps -> f (bf16 hi/lo planes)
    gather_f_kernel<<<256, 256>>>(cb0, cb1, cb2, cb3);

    // 4) uv(2048x128) = f(2048x256) @ Wuv  (64x64 tiles -> 64 CTAs)
    gemm_bf_kernel<64><<<dim3(128 / 64, ROWS / 64), 256,
                         GEMM_SMEM_BYTES_64>>>(
        fh, fl, Wuvh, Wuvl, uvb, ROWS, 128, MM);

    // 5) pair stage + fused head (mma.sync fp16 2-term)
    cudaFuncSetAttribute(pair_mma_kernel,
                         cudaFuncAttributeMaxDynamicSharedMemorySize,
                         PAIR_SMEM_BYTES);
    pair_mma_kernel<<<dim3(16, 16), 128, PAIR_SMEM_BYTES>>>(
        uvb, mw1, mw2, mw3, mb0, mb1, mb2, mb3,
        lw0, lb0, lw1, lb1, out);
}

// round 8
// speedup vs baseline: 1.2740x; 1.2740x over previous
#include <cuda_runtime.h>
#include <cuda_bf16.h>
#include <cstdint>

// ---------------------------------------------------------------------------
// RelationLayer: L=128, B=16, E=512, C=64, KERNELS={1,3,5,7}, M=256, OUT=256
//  1) prep: split x -> bf16 hi/lo, repack conv weights, pack Wuv  (1 launch)
//  2) G = x(2048x512) @ Wr               (bf16 3-term GEMM, 128x128 tiles)
//  3) f = lrelu(gather taps + bias) -> bf16 hi/lo planes
//  4) uv = f(2048x256) @ Wuv(256x128)    (bf16 3-term GEMM, 64x64 tiles)
//  5) pair kernel (round-6): mma.sync bf16 3-term, packed uint4 weight
//     fragments, per-jt barriers, in-register layer chaining, fused head.
// ---------------------------------------------------------------------------

#define LL 128
#define BB 16
#define EE 512
#define MM 256
#define ROWS 2048
#define GCOLS 1024

#define NX (ROWS * EE)
#define NW (EE * GCOLS)
#define NU (128 * MM)
#define NF (ROWS * MM)

__device__ float g_G[ROWS * GCOLS];
__device__ float g_uv[ROWS * 128];
__device__ __nv_bfloat16 g_xh[NX];
__device__ __nv_bfloat16 g_xl[NX];
__device__ __nv_bfloat16 g_fh[NF];
__device__ __nv_bfloat16 g_fl[NF];
__device__ __nv_bfloat16 g_Wrh[NW];
__device__ __nv_bfloat16 g_Wrl[NW];
__device__ __nv_bfloat16 g_Wuvh[NU];
__device__ __nv_bfloat16 g_Wuvl[NU];

// ===================== helpers ==============================================
__device__ __forceinline__ float lrelu(float x) { return fmaxf(x, 0.1f * x); }

// split two f32 into bf16-hi word and bf16-lo (residual) word
__device__ __forceinline__ void split2(float x0, float x1,
                                       uint32_t& hiw, uint32_t& low) {
    __nv_bfloat16 h0 = __float2bfloat16(x0);
    __nv_bfloat16 h1 = __float2bfloat16(x1);
    float r0 = x0 - __bfloat162float(h0);
    float r1 = x1 - __bfloat162float(h1);
    __nv_bfloat16 l0 = __float2bfloat16(r0);
    __nv_bfloat16 l1 = __float2bfloat16(r1);
    __nv_bfloat162 hp; hp.x = h0; hp.y = h1;
    __nv_bfloat162 lp; lp.x = l0; lp.y = l1;
    hiw = *(uint32_t*)&hp;
    low = *(uint32_t*)&lp;
}

__device__ __forceinline__ void split1(float v, __nv_bfloat16& h, __nv_bfloat16& l) {
    h = __float2bfloat16(v);
    l = __float2bfloat16(v - __bfloat162float(h));
}

// mma.sync m16n8k16 bf16 -> f32 accumulate (baseline PTX, no 'a' feature)
__device__ __forceinline__ void mma16816(float c[4], const uint32_t a[4],
                                         uint32_t b0, uint32_t b1) {
    asm volatile(
        "mma.sync.aligned.m16n8k16.row.col.f32.bf16.bf16.f32 "
        "{%0,%1,%2,%3}, {%4,%5,%6,%7}, {%8,%9}, {%0,%1,%2,%3};"
        : "+f"(c[0]), "+f"(c[1]), "+f"(c[2]), "+f"(c[3])
        : "r"(a[0]), "r"(a[1]), "r"(a[2]), "r"(a[3]), "r"(b0), "r"(b1));
}

// ===================== prep: splitx + repack_wr + pack_wuv ==================
__global__ void prep_kernel(const float* __restrict__ x,
                            const float* __restrict__ cw0,
                            const float* __restrict__ cw1,
                            const float* __restrict__ cw2,
                            const float* __restrict__ cw3,
                            const float* __restrict__ mw0) {
    int idx = blockIdx.x * 256 + threadIdx.x;
    if (idx < NX) {
        split1(x[idx], g_xh[idx], g_xl[idx]);
    } else if (idx < NX + NW) {
        int j = idx - NX;
        int col = j >> 9;            // n: 0..1023
        int e = j & 511;             // k
        int p = col >> 6;
        int c = col & 63;
        const float* w; int k, t;
        if (p < 1)      { w = cw0; k = 1; t = p; }
        else if (p < 4) { w = cw1; k = 3; t = p - 1; }
        else if (p < 9) { w = cw2; k = 5; t = p - 4; }
        else            { w = cw3; k = 7; t = p - 9; }
        split1(w[(c * k + t) * EE + e], g_Wrh[j], g_Wrl[j]);
    } else if (idx < NX + NW + NU) {
        int j = idx - NX - NW;
        int n = j >> 8;              // 0..127
        int k = j & 255;
        float v;
        if (n < 64) v = mw0[n * 512 + k];
        else        v = mw0[(n - 64) * 512 + 256 + k];
        split1(v, g_Wuvh[j], g_Wuvl[j]);
    }
}

// ===================== tensor-core bf16-split GEMM (templated tile) ========
// C(MxN) = A(MxK) @ B(KxN), A and B given as bf16 hi/lo planes [rows][K].
// Tile T x T, K-step 64, 256 threads (8 warps, 4 along m x 2 along n).
// M%T==0, N%T==0, K%64==0. T in {64, 128}.
#define TSG 72            // padded k-stride in bf16 units

template <int T>
__global__ void __launch_bounds__(256, 1)
gemm_bf_kernel(const __nv_bfloat16* __restrict__ Ahig,
               const __nv_bfloat16* __restrict__ Alog,
               const __nv_bfloat16* __restrict__ Bhig,
               const __nv_bfloat16* __restrict__ Blog,
               float* __restrict__ C, int M, int N, int K) {
    constexpr int SAH = 0;
    constexpr int SAL = T * TSG;
    constexpr int SBH = 2 * T * TSG;
    constexpr int SBL = 3 * T * TSG;
    constexpr int MT = T / 64;       // m16x2 tiles per warp
    constexpr int NT = T / 16;       // n8 tiles per warp
    constexpr int IT = T / 32;       // loader iterations per plane

    extern __shared__ __nv_bfloat16 sm[];
    int tid = threadIdx.x, w = tid >> 5, lane = tid & 31;
    int g = lane >> 2, t4 = lane & 3;
    int m0 = blockIdx.y * T, n0 = blockIdx.x * T;
    int mw = (w & 3) * (T / 4);
    int nw = (w >> 2) * (T / 2);

    float Cc[MT][NT][4];
#pragma unroll
    for (int mt = 0; mt < MT; mt++)
#pragma unroll
        for (int nt = 0; nt < NT; nt++)
#pragma unroll
            for (int q = 0; q < 4; q++) Cc[mt][nt][q] = 0.f;

    for (int k0 = 0; k0 < K; k0 += 64) {
        uint4 ah[IT], al[IT], bh[IT], bl[IT];
#pragma unroll
        for (int it = 0; it < IT; it++) {
            int u = tid + it * 256;
            int row = u >> 3;
            int kq = (u & 7) * 8;
            ah[it] = *(const uint4*)(Ahig + (m0 + row) * K + k0 + kq);
            al[it] = *(const uint4*)(Alog + (m0 + row) * K + k0 + kq);
            bh[it] = *(const uint4*)(Bhig + (n0 + row) * K + k0 + kq);
            bl[it] = *(const uint4*)(Blog + (n0 + row) * K + k0 + kq);
        }
        __syncthreads();
#pragma unroll
        for (int it = 0; it < IT; it++) {
            int u = tid + it * 256;
            int row = u >> 3;
            int kq = (u & 7) * 8;
            int base = row * TSG + kq;
            *(uint4*)&sm[SAH + base] = ah[it];
            *(uint4*)&sm[SAL + base] = al[it];
            *(uint4*)&sm[SBH + base] = bh[it];
            *(uint4*)&sm[SBL + base] = bl[it];
        }
        __syncthreads();

#pragma unroll
        for (int kc = 0; kc < 4; kc++) {
            int kk = kc * 16 + 2 * t4;
            uint32_t Ahi[MT][4], Alo[MT][4];
#pragma unroll
            for (int mt = 0; mt < MT; mt++) {
                int r0 = mw + mt * 16 + g;
                int r1 = r0 + 8;
                Ahi[mt][0] = *(const uint32_t*)&sm[SAH + r0 * TSG + kk];
                Ahi[mt][1] = *(const uint32_t*)&sm[SAH + r1 * TSG + kk];
                Ahi[mt][2] = *(const uint32_t*)&sm[SAH + r0 * TSG + kk + 8];
                Ahi[mt][3] = *(const uint32_t*)&sm[SAH + r1 * TSG + kk + 8];
                Alo[mt][0] = *(const uint32_t*)&sm[SAL + r0 * TSG + kk];
                Alo[mt][1] = *(const uint32_t*)&sm[SAL + r1 * TSG + kk];
                Alo[mt][2] = *(const uint32_t*)&sm[SAL + r0 * TSG + kk + 8];
                Alo[mt][3] = *(const uint32_t*)&sm[SAL + r1 * TSG + kk + 8];
            }
#pragma unroll
            for (int nt = 0; nt < NT; nt++) {
                int nrow = nw + nt * 8 + g;
                uint32_t bh0 = *(const uint32_t*)&sm[SBH + nrow * TSG + kk];
                uint32_t bh1 = *(const uint32_t*)&sm[SBH + nrow * TSG + kk + 8];
                uint32_t bl0 = *(const uint32_t*)&sm[SBL + nrow * TSG + kk];
                uint32_t bl1 = *(const uint32_t*)&sm[SBL + nrow * TSG + kk + 8];
#pragma unroll
                for (int mt = 0; mt < MT; mt++) {
                    mma16816(Cc[mt][nt], Ahi[mt], bh0, bh1);
                    mma16816(Cc[mt][nt], Ahi[mt], bl0, bl1);
                    mma16816(Cc[mt][nt], Alo[mt], bh0, bh1);
                }
            }
        }
    }

    // epilogue: write f32
#pragma unroll
    for (int mt = 0; mt < MT; mt++) {
        int r0 = m0 + mw + mt * 16 + g;
        int r1 = r0 + 8;
#pragma unroll
        for (int nt = 0; nt < NT; nt++) {
            int col = n0 + nw + nt * 8 + 2 * t4;
            *(float2*)(C + r0 * N + col) = make_float2(Cc[mt][nt][0], Cc[mt][nt][1]);
            *(float2*)(C + r1 * N + col) = make_float2(Cc[mt][nt][2], Cc[mt][nt][3]);
        }
    }
}

#define GEMM_SMEM_BYTES_128 (4 * 128 * TSG * 2)
#define GEMM_SMEM_BYTES_64  (4 * 64 * TSG * 2)

// ===================== gather taps -> f (bf16 hi/lo, ILP 8) =================
__global__ void gather_f_kernel(const float* __restrict__ cb0,
                                const float* __restrict__ cb1,
                                const float* __restrict__ cb2,
                                const float* __restrict__ cb3) {
    int t0 = blockIdx.x * 256 + threadIdx.x;   // 0..65535
#pragma unroll
    for (int q = 0; q < 8; q++) {
        int idx = t0 + q * 65536;
        int row = idx >> 8;        // (l,b): 0..2047
        int m = idx & 255;
        int l = row >> 4, b = row & 15;
        int br = m >> 6, c = m & 63;
        int k, pad, base;
        const float* cb;
        if (br == 0)      { k = 1; base = 0; cb = cb0; }
        else if (br == 1) { k = 3; base = 1; cb = cb1; }
        else if (br == 2) { k = 5; base = 4; cb = cb2; }
        else              { k = 7; base = 9; cb = cb3; }
        pad = (k - 1) >> 1;
        float sum = cb[c];
        for (int tt = 0; tt < k; tt++) {
            int l2 = l - pad + tt;
            if ((unsigned)l2 < (unsigned)LL)
                sum += g_G[(l2 * BB + b) * GCOLS + (base + tt) * 64 + c];
        }
        split1(lrelu(sum), g_fh[idx], g_fl[idx]);
    }
}

// ===================== pair kernel (round-6, mma.sync bf16 3-term) ==========
// grid (16, 16): blockIdx.x -> j-tile of 8, blockIdx.y -> b. 128 threads.
// Warp w handles i-rows [w*32, w*32+32) as 2 m-tiles of 16.
// Weights staged as packed uint4 fragments:
//   W4[l][kc][n][t4] = {hi_b0, hi_b1, lo_b0, lo_b1} (16B per entry)
#define PV_STRIDE 132
#define P_W4   0
#define P_V    49152
#define P_U    82944
#define P_B    84992
#define P_RED  86016
#define P_SR   87040
#define P_TR   89088
#define PAIR_SMEM_BYTES 91136

__global__ void __launch_bounds__(128, 2)
pair_mma_kernel(const float* __restrict__ uv,
                const float* __restrict__ mw1, const float* __restrict__ mw2,
                const float* __restrict__ mw3,
                const float* __restrict__ mb0, const float* __restrict__ mb1,
                const float* __restrict__ mb2, const float* __restrict__ mb3,
                const float* __restrict__ lw0, const float* __restrict__ lb0,
                const float* __restrict__ lw1, const float* __restrict__ lb1,
                float* __restrict__ out) {
    extern __shared__ char smp[];
    int tid = threadIdx.x, w = tid >> 5, lane = tid & 31;
    int g = lane >> 2, t4 = lane & 3;
    int b = blockIdx.y, j0 = blockIdx.x * 8;

    // ---- stage weights as packed uint4 fragments ----
    {
        uint4* W4 = (uint4*)(smp + P_W4);
        for (int e = tid; e < 3072; e += 128) {
            int t4i = e & 3;
            int n = (e >> 2) & 63;
            int kc = (e >> 8) & 3;
            int l = e >> 10;
            const float* wsrc = (l == 0) ? mw1 : (l == 1) ? mw2 : mw3;
            int k0 = kc * 16 + 2 * t4i;
            float2 v01 = *(const float2*)(wsrc + n * 64 + k0);
            float2 v89 = *(const float2*)(wsrc + n * 64 + k0 + 8);
            uint32_t h0, l0, h1, l1;
            split2(v01.x, v01.y, h0, l0);
            split2(v89.x, v89.y, h1, l1);
            uint4 pk; pk.x = h0; pk.y = h1; pk.z = l0; pk.w = l1;
            W4[e] = pk;
        }
    }
    // ---- stage V[k][i] (f32, stride 132) ----
    {
        float* V = (float*)(smp + P_V);
        const float* vp = uv + (tid * BB + b) * 128 + 64;
#pragma unroll
        for (int q = 0; q < 16; q++) {
            float4 v4 = *(const float4*)(vp + q * 4);
            V[(q * 4 + 0) * PV_STRIDE + tid] = v4.x;
            V[(q * 4 + 1) * PV_STRIDE + tid] = v4.y;
            V[(q * 4 + 2) * PV_STRIDE + tid] = v4.z;
            V[(q * 4 + 3) * PV_STRIDE + tid] = v4.w;
        }
    }
    if (tid < 64) {
        float* U = (float*)(smp + P_U);
#pragma unroll
        for (int jt = 0; jt < 8; jt++)
            U[jt * 64 + tid] = uv[((j0 + jt) * BB + b) * 128 + tid];
        float* Bs = (float*)(smp + P_B);
        Bs[tid] = mb0[tid];
        Bs[64 + tid] = mb1[tid];
        Bs[128 + tid] = mb2[tid];
        Bs[192 + tid] = mb3[tid];
    }
    __syncthreads();

    const float* V = (const float*)(smp + P_V);
    const float* U = (const float*)(smp + P_U);
    const float* BIAS = (const float*)(smp + P_B);
    const uint4* W4 = (const uint4*)(smp + P_W4);
    float* RED = (float*)(smp + P_RED);
    float* SR = (float*)(smp + P_SR);

    for (int jt = 0; jt < 8; jt++) {
        uint32_t Ahi[2][4][4], Alo[2][4][4];

        // ---- layer-1 A fragments: x = lrelu(u + v + b0) ----
#pragma unroll
        for (int mt = 0; mt < 2; mt++) {
            int r0 = w * 32 + mt * 16 + g;
            int r1 = r0 + 8;
#pragma unroll
            for (int kc = 0; kc < 4; kc++) {
                int k0 = kc * 16 + 2 * t4;
                float ub0 = U[jt * 64 + k0]     + BIAS[k0];
                float ub1 = U[jt * 64 + k0 + 1] + BIAS[k0 + 1];
                float ub8 = U[jt * 64 + k0 + 8] + BIAS[k0 + 8];
                float ub9 = U[jt * 64 + k0 + 9] + BIAS[k0 + 9];
                float x00 = lrelu(ub0 + V[k0 * PV_STRIDE + r0]);
                float x01 = lrelu(ub1 + V[(k0 + 1) * PV_STRIDE + r0]);
                float x10 = lrelu(ub0 + V[k0 * PV_STRIDE + r1]);
                float x11 = lrelu(ub1 + V[(k0 + 1) * PV_STRIDE + r1]);
                float x08 = lrelu(ub8 + V[(k0 + 8) * PV_STRIDE + r0]);
                float x09 = lrelu(ub9 + V[(k0 + 9) * PV_STRIDE + r0]);
                float x18 = lrelu(ub8 + V[(k0 + 8) * PV_STRIDE + r1]);
                float x19 = lrelu(ub9 + V[(k0 + 9) * PV_STRIDE + r1]);
                split2(x00, x01, Ahi[mt][kc][0], Alo[mt][kc][0]);
                split2(x10, x11, Ahi[mt][kc][1], Alo[mt][kc][1]);
                split2(x08, x09, Ahi[mt][kc][2], Alo[mt][kc][2]);
                split2(x18, x19, Ahi[mt][kc][3], Alo[mt][kc][3]);
            }
        }

        // ---- 3 chained MMA layers ----
        float Cc[2][8][4];
#pragma unroll
        for (int l = 0; l < 3; l++) {
#pragma unroll
            for (int mt = 0; mt < 2; mt++)
#pragma unroll
                for (int nt = 0; nt < 8; nt++)
#pragma unroll
                    for (int q = 0; q < 4; q++) Cc[mt][nt][q] = 0.f;

#pragma unroll
            for (int kc = 0; kc < 4; kc++) {
#pragma unroll
                for (int nt = 0; nt < 8; nt++) {
                    uint4 wq = W4[((l * 4 + kc) * 64 + nt * 8 + g) * 4 + t4];
                    mma16816(Cc[0][nt], Ahi[0][kc], wq.x, wq.y);
                    mma16816(Cc[1][nt], Ahi[1][kc], wq.x, wq.y);
                    mma16816(Cc[0][nt], Ahi[0][kc], wq.z, wq.w);
                    mma16816(Cc[1][nt], Ahi[1][kc], wq.z, wq.w);
                    mma16816(Cc[0][nt], Alo[0][kc], wq.x, wq.y);
                    mma16816(Cc[1][nt], Alo[1][kc], wq.x, wq.y);
                }
            }

            if (l < 2) {
                const float* bl = BIAS + 64 * (l + 1);
#pragma unroll
                for (int nt = 0; nt < 8; nt++) {
                    int col = nt * 8 + 2 * t4;
                    float bx = bl[col], by = bl[col + 1];
                    int kc2 = nt >> 1, ri = (nt & 1) * 2;
#pragma unroll
                    for (int mt = 0; mt < 2; mt++) {
                        float h0 = lrelu(Cc[mt][nt][0] + bx);
                        float h1 = lrelu(Cc[mt][nt][1] + by);
                        float h2 = lrelu(Cc[mt][nt][2] + bx);
                        float h3 = lrelu(Cc[mt][nt][3] + by);
                        split2(h0, h1, Ahi[mt][kc2][ri], Alo[mt][kc2][ri]);
                        split2(h2, h3, Ahi[mt][kc2][ri + 1], Alo[mt][kc2][ri + 1]);
                    }
                }
            }
        }

        // ---- final: bias + lrelu, reduce over i ----
        {
            const float* bl = BIAS + 192;
#pragma unroll
            for (int nt = 0; nt < 8; nt++) {
                int col = nt * 8 + 2 * t4;
                float bx = bl[col], by = bl[col + 1];
                float s0 = lrelu(Cc[0][nt][0] + bx) + lrelu(Cc[0][nt][2] + bx) +
                           lrelu(Cc[1][nt][0] + bx) + lrelu(Cc[1][nt][2] + bx);
                float s1 = lrelu(Cc[0][nt][1] + by) + lrelu(Cc[0][nt][3] + by) +
                           lrelu(Cc[1][nt][1] + by) + lrelu(Cc[1][nt][3] + by);
                s0 += __shfl_xor_sync(0xffffffffu, s0, 4);
                s0 += __shfl_xor_sync(0xffffffffu, s0, 8);
                s0 += __shfl_xor_sync(0xffffffffu, s0, 16);
                s1 += __shfl_xor_sync(0xffffffffu, s1, 4);
                s1 += __shfl_xor_sync(0xffffffffu, s1, 8);
                s1 += __shfl_xor_sync(0xffffffffu, s1, 16);
                if (lane < 4) {
                    RED[w * 64 + col] = s0;
                    RED[w * 64 + col + 1] = s1;
                }
            }
        }
        __syncthreads();
        if (tid < 64) {
            float s = RED[tid] + RED[64 + tid] + RED[128 + tid] + RED[192 + tid];
            SR[jt * 64 + tid] = s;
        }
        __syncthreads();
    }

    // ---- fused head: t = lrelu(s@lw0.T+lb0); out = lrelu(t@lw1.T+lb1) ----
    float* TR = (float*)(smp + P_TR);
#pragma unroll
    for (int q = 0; q < 4; q++) {
        int idx = tid + 128 * q;
        int jt = idx >> 6, o = idx & 63;
        const float* wr = lw0 + o * 64;
        float acc = lb0[o];
#pragma unroll
        for (int c = 0; c < 64; c += 4) {
            float4 w4 = *(const float4*)(wr + c);
            acc += SR[jt * 64 + c] * w4.x + SR[jt * 64 + c + 1] * w4.y +
                   SR[jt * 64 + c + 2] * w4.z + SR[jt * 64 + c + 3] * w4.w;
        }
        TR[idx] = lrelu(acc);
    }
    __syncthreads();
#pragma unroll
    for (int q = 0; q < 16; q++) {
        int idx = tid + 128 * q;
        int jt = idx >> 8, o = idx & 255;
        const float* wr = lw1 + o * 64;
        float acc = lb1[o];
#pragma unroll
        for (int c = 0; c < 64; c += 4) {
            float4 w4 = *(const float4*)(wr + c);
            acc += TR[jt * 64 + c] * w4.x + TR[jt * 64 + c + 1] * w4.y +
                   TR[jt * 64 + c + 2] * w4.z + TR[jt * 64 + c + 3] * w4.w;
        }
        out[((j0 + jt) * BB + b) * 256 + o] = lrelu(acc);
    }
}

// ===================== host launch ==========================================
extern "C" void kernel_launch(void* const* d_in, const int* in_sizes, int n_in,
                              void* d_out, int out_size) {
    const float* x   = (const float*)d_in[0];
    const float* cw0 = (const float*)d_in[1];
    const float* cb0 = (const float*)d_in[2];
    const float* cw1 = (const float*)d_in[3];
    const float* cb1 = (const float*)d_in[4];
    const float* cw2 = (const float*)d_in[5];
    const float* cb2 = (const float*)d_in[6];
    const float* cw3 = (const float*)d_in[7];
    const float* cb3 = (const float*)d_in[8];
    const float* mw0 = (const float*)d_in[9];
    const float* mb0 = (const float*)d_in[10];
    const float* mw1 = (const float*)d_in[11];
    const float* mb1 = (const float*)d_in[12];
    const float* mw2 = (const float*)d_in[13];
    const float* mb2 = (const float*)d_in[14];
    const float* mw3 = (const float*)d_in[15];
    const float* mb3 = (const float*)d_in[16];
    const float* lw0 = (const float*)d_in[17];
    const float* lb0 = (const float*)d_in[18];
    const float* lw1 = (const float*)d_in[19];
    const float* lb1 = (const float*)d_in[20];
    float* out = (float*)d_out;

    float *G, *uvb;
    __nv_bfloat16 *xh, *xl, *fh, *fl, *Wrh, *Wrl, *Wuvh, *Wuvl;
    cudaGetSymbolAddress((void**)&G, g_G);
    cudaGetSymbolAddress((void**)&uvb, g_uv);
    cudaGetSymbolAddress((void**)&xh, g_xh);
    cudaGetSymbolAddress((void**)&xl, g_xl);
    cudaGetSymbolAddress((void**)&fh, g_fh);
    cudaGetSymbolAddress((void**)&fl, g_fl);
    cudaGetSymbolAddress((void**)&Wrh, g_Wrh);
    cudaGetSymbolAddress((void**)&Wrl, g_Wrl);
    cudaGetSymbolAddress((void**)&Wuvh, g_Wuvh);
    cudaGetSymbolAddress((void**)&Wuvl, g_Wuvl);

    // 1) prep (split x, repack conv weights, pack Wuv)
    prep_kernel<<<(NX + NW + NU + 255) / 256, 256>>>(x, cw0, cw1, cw2, cw3, mw0);

    cudaFuncSetAttribute(gemm_bf_kernel<128>,
                         cudaFuncAttributeMaxDynamicSharedMemorySize,
                         GEMM_SMEM_BYTES_128);
    cudaFuncSetAttribute(gemm_bf_kernel<64>,
                         cudaFuncAttributeMaxDynamicSharedMemorySize,
                         GEMM_SMEM_BYTES_64);

    // 2) conv as GEMM: G(2048x1024) = x(2048x512) @ Wr  (128x128 tiles)
    gemm_bf_kernel<128><<<dim3(GCOLS / 128, ROWS / 128), 256,
                          GEMM_SMEM_BYTES_128>>>(
        xh, xl, Wrh, Wrl, G, ROWS, GCOLS, EE);

    // 3) gather taps -> f (bf16 hi/lo planes)
    gather_f_kernel<<<256, 256>>>(cb0, cb1, cb2, cb3);

    // 4) uv(2048x128) = f(2048x256) @ Wuv  (64x64 tiles -> 64 CTAs)
    gemm_bf_kernel<64><<<dim3(128 / 64, ROWS / 64), 256,
                         GEMM_SMEM_BYTES_64>>>(
        fh, fl, Wuvh, Wuvl, uvb, ROWS, 128, MM);

    // 5) pair stage + fused head (round-6 pair kernel)
    cudaFuncSetAttribute(pair_mma_kernel,
                         cudaFuncAttributeMaxDynamicSharedMemorySize,
                         PAIR_SMEM_BYTES);
    pair_mma_kernel<<<dim3(16, 16), 128, PAIR_SMEM_BYTES>>>(
        uvb, mw1, mw2, mw3, mb0, mb1, mb2, mb3,
        lw0, lb0, lw1, lb1, out);
}

// round 9
// speedup vs baseline: 1.5111x; 1.1861x over previous
#include <cuda_runtime.h>
#include <cuda_bf16.h>
#include <cuda_fp16.h>
#include <cstdint>

// ---------------------------------------------------------------------------
// RelationLayer: L=128, B=16, E=512, C=64, KERNELS={1,3,5,7}, M=256, OUT=256
//  1) prep: split x -> bf16 hi/lo, repack conv weights, pack Wuv  (1 launch)
//  2) G = x(2048x512) @ Wr               (bf16 3-term GEMM, 128x128 tiles)
//  3) f = lrelu(gather taps + bias) -> bf16 hi/lo planes
//  4) uv = f(2048x256) @ Wuv(256x128)    (bf16 3-term GEMM, 64x64 tiles)
//  5) pair kernel: round-6 STRUCTURE (per-jt barriers, 1KB RED) with fp16
//     2-term MMA only (A single fp16, W fp16 hi/lo -> 4 mma per tile).
// ---------------------------------------------------------------------------

#define LL 128
#define BB 16
#define EE 512
#define MM 256
#define ROWS 2048
#define GCOLS 1024

#define NX (ROWS * EE)
#define NW (EE * GCOLS)
#define NU (128 * MM)
#define NF (ROWS * MM)

__device__ float g_G[ROWS * GCOLS];
__device__ float g_uv[ROWS * 128];
__device__ __nv_bfloat16 g_xh[NX];
__device__ __nv_bfloat16 g_xl[NX];
__device__ __nv_bfloat16 g_fh[NF];
__device__ __nv_bfloat16 g_fl[NF];
__device__ __nv_bfloat16 g_Wrh[NW];
__device__ __nv_bfloat16 g_Wrl[NW];
__device__ __nv_bfloat16 g_Wuvh[NU];
__device__ __nv_bfloat16 g_Wuvl[NU];

// ===================== helpers ==============================================
__device__ __forceinline__ float lrelu(float x) { return fmaxf(x, 0.1f * x); }

// split two f32 into bf16-hi word and bf16-lo (residual) word
__device__ __forceinline__ void split2(float x0, float x1,
                                       uint32_t& hiw, uint32_t& low) {
    __nv_bfloat16 h0 = __float2bfloat16(x0);
    __nv_bfloat16 h1 = __float2bfloat16(x1);
    float r0 = x0 - __bfloat162float(h0);
    float r1 = x1 - __bfloat162float(h1);
    __nv_bfloat16 l0 = __float2bfloat16(r0);
    __nv_bfloat16 l1 = __float2bfloat16(r1);
    __nv_bfloat162 hp; hp.x = h0; hp.y = h1;
    __nv_bfloat162 lp; lp.x = l0; lp.y = l1;
    hiw = *(uint32_t*)&hp;
    low = *(uint32_t*)&lp;
}

__device__ __forceinline__ void split1(float v, __nv_bfloat16& h, __nv_bfloat16& l) {
    h = __float2bfloat16(v);
    l = __float2bfloat16(v - __bfloat162float(h));
}

// pack two f32 into one fp16x2 word (low 16 bits = first element)
__device__ __forceinline__ uint32_t packh2(float a, float b) {
    __half2 h = __floats2half2_rn(a, b);
    return *(uint32_t*)&h;
}
// split two f32 into fp16-hi word and fp16-lo (residual) word
__device__ __forceinline__ void splith2(float a, float b,
                                        uint32_t& hi, uint32_t& lo) {
    __half ha = __float2half_rn(a), hb = __float2half_rn(b);
    __half la = __float2half_rn(a - __half2float(ha));
    __half lb = __float2half_rn(b - __half2float(hb));
    __half2 hp = __halves2half2(ha, hb);
    __half2 lp = __halves2half2(la, lb);
    hi = *(uint32_t*)&hp;
    lo = *(uint32_t*)&lp;
}

// mma.sync m16n8k16 bf16 -> f32 accumulate (baseline PTX)
__device__ __forceinline__ void mma16816(float c[4], const uint32_t a[4],
                                         uint32_t b0, uint32_t b1) {
    asm volatile(
        "mma.sync.aligned.m16n8k16.row.col.f32.bf16.bf16.f32 "
        "{%0,%1,%2,%3}, {%4,%5,%6,%7}, {%8,%9}, {%0,%1,%2,%3};"
        : "+f"(c[0]), "+f"(c[1]), "+f"(c[2]), "+f"(c[3])
        : "r"(a[0]), "r"(a[1]), "r"(a[2]), "r"(a[3]), "r"(b0), "r"(b1));
}
// mma.sync m16n8k16 fp16 -> f32 accumulate (baseline PTX)
__device__ __forceinline__ void mmah(float c[4], const uint32_t a[4],
                                     uint32_t b0, uint32_t b1) {
    asm volatile(
        "mma.sync.aligned.m16n8k16.row.col.f32.f16.f16.f32 "
        "{%0,%1,%2,%3}, {%4,%5,%6,%7}, {%8,%9}, {%0,%1,%2,%3};"
        : "+f"(c[0]), "+f"(c[1]), "+f"(c[2]), "+f"(c[3])
        : "r"(a[0]), "r"(a[1]), "r"(a[2]), "r"(a[3]), "r"(b0), "r"(b1));
}

// ===================== prep: splitx + repack_wr + pack_wuv ==================
__global__ void prep_kernel(const float* __restrict__ x,
                            const float* __restrict__ cw0,
                            const float* __restrict__ cw1,
                            const float* __restrict__ cw2,
                            const float* __restrict__ cw3,
                            const float* __restrict__ mw0) {
    int idx = blockIdx.x * 256 + threadIdx.x;
    if (idx < NX) {
        split1(x[idx], g_xh[idx], g_xl[idx]);
    } else if (idx < NX + NW) {
        int j = idx - NX;
        int col = j >> 9;            // n: 0..1023
        int e = j & 511;             // k
        int p = col >> 6;
        int c = col & 63;
        const float* w; int k, t;
        if (p < 1)      { w = cw0; k = 1; t = p; }
        else if (p < 4) { w = cw1; k = 3; t = p - 1; }
        else if (p < 9) { w = cw2; k = 5; t = p - 4; }
        else            { w = cw3; k = 7; t = p - 9; }
        split1(w[(c * k + t) * EE + e], g_Wrh[j], g_Wrl[j]);
    } else if (idx < NX + NW + NU) {
        int j = idx - NX - NW;
        int n = j >> 8;              // 0..127
        int k = j & 255;
        float v;
        if (n < 64) v = mw0[n * 512 + k];
        else        v = mw0[(n - 64) * 512 + 256 + k];
        split1(v, g_Wuvh[j], g_Wuvl[j]);
    }
}

// ===================== tensor-core bf16-split GEMM (templated tile) ========
#define TSG 72            // padded k-stride in bf16 units

template <int T>
__global__ void __launch_bounds__(256, 1)
gemm_bf_kernel(const __nv_bfloat16* __restrict__ Ahig,
               const __nv_bfloat16* __restrict__ Alog,
               const __nv_bfloat16* __restrict__ Bhig,
               const __nv_bfloat16* __restrict__ Blog,
               float* __restrict__ C, int M, int N, int K) {
    constexpr int SAH = 0;
    constexpr int SAL = T * TSG;
    constexpr int SBH = 2 * T * TSG;
    constexpr int SBL = 3 * T * TSG;
    constexpr int MT = T / 64;
    constexpr int NT = T / 16;
    constexpr int IT = T / 32;

    extern __shared__ __nv_bfloat16 sm[];
    int tid = threadIdx.x, w = tid >> 5, lane = tid & 31;
    int g = lane >> 2, t4 = lane & 3;
    int m0 = blockIdx.y * T, n0 = blockIdx.x * T;
    int mw = (w & 3) * (T / 4);
    int nw = (w >> 2) * (T / 2);

    float Cc[MT][NT][4];
#pragma unroll
    for (int mt = 0; mt < MT; mt++)
#pragma unroll
        for (int nt = 0; nt < NT; nt++)
#pragma unroll
            for (int q = 0; q < 4; q++) Cc[mt][nt][q] = 0.f;

    for (int k0 = 0; k0 < K; k0 += 64) {
        uint4 ah[IT], al[IT], bh[IT], bl[IT];
#pragma unroll
        for (int it = 0; it < IT; it++) {
            int u = tid + it * 256;
            int row = u >> 3;
            int kq = (u & 7) * 8;
            ah[it] = *(const uint4*)(Ahig + (m0 + row) * K + k0 + kq);
            al[it] = *(const uint4*)(Alog + (m0 + row) * K + k0 + kq);
            bh[it] = *(const uint4*)(Bhig + (n0 + row) * K + k0 + kq);
            bl[it] = *(const uint4*)(Blog + (n0 + row) * K + k0 + kq);
        }
        __syncthreads();
#pragma unroll
        for (int it = 0; it < IT; it++) {
            int u = tid + it * 256;
            int row = u >> 3;
            int kq = (u & 7) * 8;
            int base = row * TSG + kq;
            *(uint4*)&sm[SAH + base] = ah[it];
            *(uint4*)&sm[SAL + base] = al[it];
            *(uint4*)&sm[SBH + base] = bh[it];
            *(uint4*)&sm[SBL + base] = bl[it];
        }
        __syncthreads();

#pragma unroll
        for (int kc = 0; kc < 4; kc++) {
            int kk = kc * 16 + 2 * t4;
            uint32_t Ahi[MT][4], Alo[MT][4];
#pragma unroll
            for (int mt = 0; mt < MT; mt++) {
                int r0 = mw + mt * 16 + g;
                int r1 = r0 + 8;
                Ahi[mt][0] = *(const uint32_t*)&sm[SAH + r0 * TSG + kk];
                Ahi[mt][1] = *(const uint32_t*)&sm[SAH + r1 * TSG + kk];
                Ahi[mt][2] = *(const uint32_t*)&sm[SAH + r0 * TSG + kk + 8];
                Ahi[mt][3] = *(const uint32_t*)&sm[SAH + r1 * TSG + kk + 8];
                Alo[mt][0] = *(const uint32_t*)&sm[SAL + r0 * TSG + kk];
                Alo[mt][1] = *(const uint32_t*)&sm[SAL + r1 * TSG + kk];
                Alo[mt][2] = *(const uint32_t*)&sm[SAL + r0 * TSG + kk + 8];
                Alo[mt][3] = *(const uint32_t*)&sm[SAL + r1 * TSG + kk + 8];
            }
#pragma unroll
            for (int nt = 0; nt < NT; nt++) {
                int nrow = nw + nt * 8 + g;
                uint32_t bh0 = *(const uint32_t*)&sm[SBH + nrow * TSG + kk];
                uint32_t bh1 = *(const uint32_t*)&sm[SBH + nrow * TSG + kk + 8];
                uint32_t bl0 = *(const uint32_t*)&sm[SBL + nrow * TSG + kk];
                uint32_t bl1 = *(const uint32_t*)&sm[SBL + nrow * TSG + kk + 8];
#pragma unroll
                for (int mt = 0; mt < MT; mt++) {
                    mma16816(Cc[mt][nt], Ahi[mt], bh0, bh1);
                    mma16816(Cc[mt][nt], Ahi[mt], bl0, bl1);
                    mma16816(Cc[mt][nt], Alo[mt], bh0, bh1);
                }
            }
        }
    }

#pragma unroll
    for (int mt = 0; mt < MT; mt++) {
        int r0 = m0 + mw + mt * 16 + g;
        int r1 = r0 + 8;
#pragma unroll
        for (int nt = 0; nt < NT; nt++) {
            int col = n0 + nw + nt * 8 + 2 * t4;
            *(float2*)(C + r0 * N + col) = make_float2(Cc[mt][nt][0], Cc[mt][nt][1]);
            *(float2*)(C + r1 * N + col) = make_float2(Cc[mt][nt][2], Cc[mt][nt][3]);
        }
    }
}

#define GEMM_SMEM_BYTES_128 (4 * 128 * TSG * 2)
#define GEMM_SMEM_BYTES_64  (4 * 64 * TSG * 2)

// ===================== gather taps -> f (bf16 hi/lo, ILP 8) =================
__global__ void gather_f_kernel(const float* __restrict__ cb0,
                                const float* __restrict__ cb1,
                                const float* __restrict__ cb2,
                                const float* __restrict__ cb3) {
    int t0 = blockIdx.x * 256 + threadIdx.x;   // 0..65535
#pragma unroll
    for (int q = 0; q < 8; q++) {
        int idx = t0 + q * 65536;
        int row = idx >> 8;        // (l,b): 0..2047
        int m = idx & 255;
        int l = row >> 4, b = row & 15;
        int br = m >> 6, c = m & 63;
        int k, pad, base;
        const float* cb;
        if (br == 0)      { k = 1; base = 0; cb = cb0; }
        else if (br == 1) { k = 3; base = 1; cb = cb1; }
        else if (br == 2) { k = 5; base = 4; cb = cb2; }
        else              { k = 7; base = 9; cb = cb3; }
        pad = (k - 1) >> 1;
        float sum = cb[c];
        for (int tt = 0; tt < k; tt++) {
            int l2 = l - pad + tt;
            if ((unsigned)l2 < (unsigned)LL)
                sum += g_G[(l2 * BB + b) * GCOLS + (base + tt) * 64 + c];
        }
        split1(lrelu(sum), g_fh[idx], g_fl[idx]);
    }
}

// ===================== pair kernel (round-6 structure, fp16 2-term MMA) =====
// grid (16, 16): blockIdx.x -> j-tile of 8, blockIdx.y -> b. 128 threads.
// Warp w handles i-rows [w*32, w*32+32) as 2 m-tiles of 16.
// Weights staged as packed uint4 fragments (fp16 hi/lo):
//   W4[l][kc][n][t4] = {wh_b0, wh_b1, wl_b0, wl_b1} (16B per entry)
// Activations: single fp16 fragments (D = A*Wh + A*Wl -> 4 mma per tile).
#define PV_STRIDE 132
#define P_W4   0
#define P_V    49152
#define P_U    82944
#define P_B    84992
#define P_RED  86016
#define P_SR   87040
#define P_TR   89088
#define PAIR_SMEM_BYTES 91136

__global__ void __launch_bounds__(128, 2)
pair_mma_kernel(const float* __restrict__ uv,
                const float* __restrict__ mw1, const float* __restrict__ mw2,
                const float* __restrict__ mw3,
                const float* __restrict__ mb0, const float* __restrict__ mb1,
                const float* __restrict__ mb2, const float* __restrict__ mb3,
                const float* __restrict__ lw0, const float* __restrict__ lb0,
                const float* __restrict__ lw1, const float* __restrict__ lb1,
                float* __restrict__ out) {
    extern __shared__ char smp[];
    int tid = threadIdx.x, w = tid >> 5, lane = tid & 31;
    int g = lane >> 2, t4 = lane & 3;
    int b = blockIdx.y, j0 = blockIdx.x * 8;

    // ---- stage weights as packed uint4 fragments (fp16 hi/lo) ----
    {
        uint4* W4 = (uint4*)(smp + P_W4);
        for (int e = tid; e < 3072; e += 128) {
            int t4i = e & 3;
            int n = (e >> 2) & 63;
            int kc = (e >> 8) & 3;
            int l = e >> 10;
            const float* wsrc = (l == 0) ? mw1 : (l == 1) ? mw2 : mw3;
            int k0 = kc * 16 + 2 * t4i;
            float2 v01 = *(const float2*)(wsrc + n * 64 + k0);
            float2 v89 = *(const float2*)(wsrc + n * 64 + k0 + 8);
            uint32_t h0, l0, h1, l1;
            splith2(v01.x, v01.y, h0, l0);
            splith2(v89.x, v89.y, h1, l1);
            uint4 pk; pk.x = h0; pk.y = h1; pk.z = l0; pk.w = l1;
            W4[e] = pk;
        }
    }
    // ---- stage V[k][i] (f32, stride 132) ----
    {
        float* V = (float*)(smp + P_V);
        const float* vp = uv + (tid * BB + b) * 128 + 64;
#pragma unroll
        for (int q = 0; q < 16; q++) {
            float4 v4 = *(const float4*)(vp + q * 4);
            V[(q * 4 + 0) * PV_STRIDE + tid] = v4.x;
            V[(q * 4 + 1) * PV_STRIDE + tid] = v4.y;
            V[(q * 4 + 2) * PV_STRIDE + tid] = v4.z;
            V[(q * 4 + 3) * PV_STRIDE + tid] = v4.w;
        }
    }
    if (tid < 64) {
        float* U = (float*)(smp + P_U);
#pragma unroll
        for (int jt = 0; jt < 8; jt++)
            U[jt * 64 + tid] = uv[((j0 + jt) * BB + b) * 128 + tid];
        float* Bs = (float*)(smp + P_B);
        Bs[tid] = mb0[tid];
        Bs[64 + tid] = mb1[tid];
        Bs[128 + tid] = mb2[tid];
        Bs[192 + tid] = mb3[tid];
    }
    __syncthreads();

    const float* V = (const float*)(smp + P_V);
    const float* U = (const float*)(smp + P_U);
    const float* BIAS = (const float*)(smp + P_B);
    const uint4* W4 = (const uint4*)(smp + P_W4);
    float* RED = (float*)(smp + P_RED);
    float* SR = (float*)(smp + P_SR);

    for (int jt = 0; jt < 8; jt++) {
        uint32_t A[2][4][4];

        // ---- layer-1 A fragments: x = lrelu(u + v + b0), single fp16 ----
#pragma unroll
        for (int mt = 0; mt < 2; mt++) {
            int r0 = w * 32 + mt * 16 + g;
            int r1 = r0 + 8;
#pragma unroll
            for (int kc = 0; kc < 4; kc++) {
                int k0 = kc * 16 + 2 * t4;
                float ub0 = U[jt * 64 + k0]     + BIAS[k0];
                float ub1 = U[jt * 64 + k0 + 1] + BIAS[k0 + 1];
                float ub8 = U[jt * 64 + k0 + 8] + BIAS[k0 + 8];
                float ub9 = U[jt * 64 + k0 + 9] + BIAS[k0 + 9];
                float x00 = lrelu(ub0 + V[k0 * PV_STRIDE + r0]);
                float x01 = lrelu(ub1 + V[(k0 + 1) * PV_STRIDE + r0]);
                float x10 = lrelu(ub0 + V[k0 * PV_STRIDE + r1]);
                float x11 = lrelu(ub1 + V[(k0 + 1) * PV_STRIDE + r1]);
                float x08 = lrelu(ub8 + V[(k0 + 8) * PV_STRIDE + r0]);
                float x09 = lrelu(ub9 + V[(k0 + 9) * PV_STRIDE + r0]);
                float x18 = lrelu(ub8 + V[(k0 + 8) * PV_STRIDE + r1]);
                float x19 = lrelu(ub9 + V[(k0 + 9) * PV_STRIDE + r1]);
                A[mt][kc][0] = packh2(x00, x01);
                A[mt][kc][1] = packh2(x10, x11);
                A[mt][kc][2] = packh2(x08, x09);
                A[mt][kc][3] = packh2(x18, x19);
            }
        }

        // ---- 3 chained MMA layers (2-term: A*Wh + A*Wl) ----
        float Cc[2][8][4];
#pragma unroll
        for (int l = 0; l < 3; l++) {
#pragma unroll
            for (int mt = 0; mt < 2; mt++)
#pragma unroll
                for (int nt = 0; nt < 8; nt++)
#pragma unroll
                    for (int q = 0; q < 4; q++) Cc[mt][nt][q] = 0.f;

#pragma unroll
            for (int kc = 0; kc < 4; kc++) {
#pragma unroll
                for (int nt = 0; nt < 8; nt++) {
                    uint4 wq = W4[((l * 4 + kc) * 64 + nt * 8 + g) * 4 + t4];
                    mmah(Cc[0][nt], A[0][kc], wq.x, wq.y);
                    mmah(Cc[1][nt], A[1][kc], wq.x, wq.y);
                    mmah(Cc[0][nt], A[0][kc], wq.z, wq.w);
                    mmah(Cc[1][nt], A[1][kc], wq.z, wq.w);
                }
            }

            if (l < 2) {
                const float* bl = BIAS + 64 * (l + 1);
#pragma unroll
                for (int nt = 0; nt < 8; nt++) {
                    int col = nt * 8 + 2 * t4;
                    float bx = bl[col], by = bl[col + 1];
                    int kc2 = nt >> 1, ri = (nt & 1) * 2;
#pragma unroll
                    for (int mt = 0; mt < 2; mt++) {
                        float h0 = lrelu(Cc[mt][nt][0] + bx);
                        float h1 = lrelu(Cc[mt][nt][1] + by);
                        float h2 = lrelu(Cc[mt][nt][2] + bx);
                        float h3 = lrelu(Cc[mt][nt][3] + by);
                        A[mt][kc2][ri]     = packh2(h0, h1);
                        A[mt][kc2][ri + 1] = packh2(h2, h3);
                    }
                }
            }
        }

        // ---- final: bias + lrelu, reduce over i ----
        {
            const float* bl = BIAS + 192;
#pragma unroll
            for (int nt = 0; nt < 8; nt++) {
                int col = nt * 8 + 2 * t4;
                float bx = bl[col], by = bl[col + 1];
                float s0 = lrelu(Cc[0][nt][0] + bx) + lrelu(Cc[0][nt][2] + bx) +
                           lrelu(Cc[1][nt][0] + bx) + lrelu(Cc[1][nt][2] + bx);
                float s1 = lrelu(Cc[0][nt][1] + by) + lrelu(Cc[0][nt][3] + by) +
                           lrelu(Cc[1][nt][1] + by) + lrelu(Cc[1][nt][3] + by);
                s0 += __shfl_xor_sync(0xffffffffu, s0, 4);
                s0 += __shfl_xor_sync(0xffffffffu, s0, 8);
                s0 += __shfl_xor_sync(0xffffffffu, s0, 16);
                s1 += __shfl_xor_sync(0xffffffffu, s1, 4);
                s1 += __shfl_xor_sync(0xffffffffu, s1, 8);
                s1 += __shfl_xor_sync(0xffffffffu, s1, 16);
                if (lane < 4) {
                    RED[w * 64 + col] = s0;
                    RED[w * 64 + col + 1] = s1;
                }
            }
        }
        __syncthreads();
        if (tid < 64) {
            float s = RED[tid] + RED[64 + tid] + RED[128 + tid] + RED[192 + tid];
            SR[jt * 64 + tid] = s;
        }
        __syncthreads();
    }

    // ---- fused head: t = lrelu(s@lw0.T+lb0); out = lrelu(t@lw1.T+lb1) ----
    float* TR = (float*)(smp + P_TR);
#pragma unroll
    for (int q = 0; q < 4; q++) {
        int idx = tid + 128 * q;
        int jt = idx >> 6, o = idx & 63;
        const float* wr = lw0 + o * 64;
        float acc = lb0[o];
#pragma unroll
        for (int c = 0; c < 64; c += 4) {
            float4 w4 = *(const float4*)(wr + c);
            acc += SR[jt * 64 + c] * w4.x + SR[jt * 64 + c + 1] * w4.y +
                   SR[jt * 64 + c + 2] * w4.z + SR[jt * 64 + c + 3] * w4.w;
        }
        TR[idx] = lrelu(acc);
    }
    __syncthreads();
#pragma unroll
    for (int q = 0; q < 16; q++) {
        int idx = tid + 128 * q;
        int jt = idx >> 8, o = idx & 255;
        const float* wr = lw1 + o * 64;
        float acc = lb1[o];
#pragma unroll
        for (int c = 0; c < 64; c += 4) {
            float4 w4 = *(const float4*)(wr + c);
            acc += TR[jt * 64 + c] * w4.x + TR[jt * 64 + c + 1] * w4.y +
                   TR[jt * 64 + c + 2] * w4.z + TR[jt * 64 + c + 3] * w4.w;
        }
        out[((j0 + jt) * BB + b) * 256 + o] = lrelu(acc);
    }
}

// ===================== host launch ==========================================
extern "C" void kernel_launch(void* const* d_in, const int* in_sizes, int n_in,
                              void* d_out, int out_size) {
    const float* x   = (const float*)d_in[0];
    const float* cw0 = (const float*)d_in[1];
    const float* cb0 = (const float*)d_in[2];
    const float* cw1 = (const float*)d_in[3];
    const float* cb1 = (const float*)d_in[4];
    const float* cw2 = (const float*)d_in[5];
    const float* cb2 = (const float*)d_in[6];
    const float* cw3 = (const float*)d_in[7];
    const float* cb3 = (const float*)d_in[8];
    const float* mw0 = (const float*)d_in[9];
    const float* mb0 = (const float*)d_in[10];
    const float* mw1 = (const float*)d_in[11];
    const float* mb1 = (const float*)d_in[12];
    const float* mw2 = (const float*)d_in[13];
    const float* mb2 = (const float*)d_in[14];
    const float* mw3 = (const float*)d_in[15];
    const float* mb3 = (const float*)d_in[16];
    const float* lw0 = (const float*)d_in[17];
    const float* lb0 = (const float*)d_in[18];
    const float* lw1 = (const float*)d_in[19];
    const float* lb1 = (const float*)d_in[20];
    float* out = (float*)d_out;

    float *G, *uvb;
    __nv_bfloat16 *xh, *xl, *fh, *fl, *Wrh, *Wrl, *Wuvh, *Wuvl;
    cudaGetSymbolAddress((void**)&G, g_G);
    cudaGetSymbolAddress((void**)&uvb, g_uv);
    cudaGetSymbolAddress((void**)&xh, g_xh);
    cudaGetSymbolAddress((void**)&xl, g_xl);
    cudaGetSymbolAddress((void**)&fh, g_fh);
    cudaGetSymbolAddress((void**)&fl, g_fl);
    cudaGetSymbolAddress((void**)&Wrh, g_Wrh);
    cudaGetSymbolAddress((void**)&Wrl, g_Wrl);
    cudaGetSymbolAddress((void**)&Wuvh, g_Wuvh);
    cudaGetSymbolAddress((void**)&Wuvl, g_Wuvl);

    // 1) prep (split x, repack conv weights, pack Wuv)
    prep_kernel<<<(NX + NW + NU + 255) / 256, 256>>>(x, cw0, cw1, cw2, cw3, mw0);

    cudaFuncSetAttribute(gemm_bf_kernel<128>,
                         cudaFuncAttributeMaxDynamicSharedMemorySize,
                         GEMM_SMEM_BYTES_128);
    cudaFuncSetAttribute(gemm_bf_kernel<64>,
                         cudaFuncAttributeMaxDynamicSharedMemorySize,
                         GEMM_SMEM_BYTES_64);

    // 2) conv as GEMM: G(2048x1024) = x(2048x512) @ Wr  (128x128 tiles)
    gemm_bf_kernel<128><<<dim3(GCOLS / 128, ROWS / 128), 256,
                          GEMM_SMEM_BYTES_128>>>(
        xh, xl, Wrh, Wrl, G, ROWS, GCOLS, EE);

    // 3) gather taps -> f (bf16 hi/lo planes)
    gather_f_kernel<<<256, 256>>>(cb0, cb1, cb2, cb3);

    // 4) uv(2048x128) = f(2048x256) @ Wuv  (64x64 tiles -> 64 CTAs)
    gemm_bf_kernel<64><<<dim3(128 / 64, ROWS / 64), 256,
                         GEMM_SMEM_BYTES_64>>>(
        fh, fl, Wuvh, Wuvl, uvb, ROWS, 128, MM);

    // 5) pair stage + fused head (fp16 2-term, round-6 structure)
    cudaFuncSetAttribute(pair_mma_kernel,
                         cudaFuncAttributeMaxDynamicSharedMemorySize,
                         PAIR_SMEM_BYTES);
    pair_mma_kernel<<<dim3(16, 16), 128, PAIR_SMEM_BYTES>>>(
        uvb, mw1, mw2, mw3, mb0, mb1, mb2, mb3,
        lw0, lb0, lw1, lb1, out);
}

// round 10
// speedup vs baseline: 1.6211x; 1.0728x over previous
#include <cuda_runtime.h>
#include <cuda_bf16.h>
#include <cuda_fp16.h>
#include <cstdint>

// ---------------------------------------------------------------------------
// RelationLayer: L=128, B=16, E=512, C=64, KERNELS={1,3,5,7}, M=256, OUT=256
//  1) prep: x -> fp16, conv weights -> fp16 hi/lo, Wuv -> fp16 hi/lo
//  2) G = x(2048x512) @ Wr               (fp16 2-term GEMM, 128x128 tiles)
//  3) f = lrelu(gather taps + bias) -> fp16
//  4) uv = f(2048x256) @ Wuv(256x128)    (fp16 2-term GEMM, 64x64 tiles)
//  5) pair kernel: round-6 structure, fp16 2-term MMA (unchanged from R9).
// ---------------------------------------------------------------------------

#define LL 128
#define BB 16
#define EE 512
#define MM 256
#define ROWS 2048
#define GCOLS 1024

#define NX (ROWS * EE)
#define NW (EE * GCOLS)
#define NU (128 * MM)
#define NF (ROWS * MM)

__device__ float g_G[ROWS * GCOLS];
__device__ float g_uv[ROWS * 128];
__device__ __half g_xf[NX];
__device__ __half g_ff[NF];
__device__ __half g_Wrh[NW];
__device__ __half g_Wrl[NW];
__device__ __half g_Wuvh[NU];
__device__ __half g_Wuvl[NU];

// ===================== helpers ==============================================
__device__ __forceinline__ float lrelu(float x) { return fmaxf(x, 0.1f * x); }

// split one f32 into fp16 hi + fp16 residual
__device__ __forceinline__ void splith1(float v, __half& h, __half& l) {
    h = __float2half_rn(v);
    l = __float2half_rn(v - __half2float(h));
}

// pack two f32 into one fp16x2 word (low 16 bits = first element)
__device__ __forceinline__ uint32_t packh2(float a, float b) {
    __half2 h = __floats2half2_rn(a, b);
    return *(uint32_t*)&h;
}
// split two f32 into fp16-hi word and fp16-lo (residual) word
__device__ __forceinline__ void splith2(float a, float b,
                                        uint32_t& hi, uint32_t& lo) {
    __half ha = __float2half_rn(a), hb = __float2half_rn(b);
    __half la = __float2half_rn(a - __half2float(ha));
    __half lb = __float2half_rn(b - __half2float(hb));
    __half2 hp = __halves2half2(ha, hb);
    __half2 lp = __halves2half2(la, lb);
    hi = *(uint32_t*)&hp;
    lo = *(uint32_t*)&lp;
}

// mma.sync m16n8k16 fp16 -> f32 accumulate (baseline PTX)
__device__ __forceinline__ void mmah(float c[4], const uint32_t a[4],
                                     uint32_t b0, uint32_t b1) {
    asm volatile(
        "mma.sync.aligned.m16n8k16.row.col.f32.f16.f16.f32 "
        "{%0,%1,%2,%3}, {%4,%5,%6,%7}, {%8,%9}, {%0,%1,%2,%3};"
        : "+f"(c[0]), "+f"(c[1]), "+f"(c[2]), "+f"(c[3])
        : "r"(a[0]), "r"(a[1]), "r"(a[2]), "r"(a[3]), "r"(b0), "r"(b1));
}

// ===================== prep: x->fp16, Wr/Wuv -> fp16 hi/lo ==================
__global__ void prep_kernel(const float* __restrict__ x,
                            const float* __restrict__ cw0,
                            const float* __restrict__ cw1,
                            const float* __restrict__ cw2,
                            const float* __restrict__ cw3,
                            const float* __restrict__ mw0) {
    int idx = blockIdx.x * 256 + threadIdx.x;
    if (idx < NX) {
        g_xf[idx] = __float2half_rn(x[idx]);
    } else if (idx < NX + NW) {
        int j = idx - NX;
        int col = j >> 9;            // n: 0..1023
        int e = j & 511;             // k
        int p = col >> 6;
        int c = col & 63;
        const float* w; int k, t;
        if (p < 1)      { w = cw0; k = 1; t = p; }
        else if (p < 4) { w = cw1; k = 3; t = p - 1; }
        else if (p < 9) { w = cw2; k = 5; t = p - 4; }
        else            { w = cw3; k = 7; t = p - 9; }
        splith1(w[(c * k + t) * EE + e], g_Wrh[j], g_Wrl[j]);
    } else if (idx < NX + NW + NU) {
        int j = idx - NX - NW;
        int n = j >> 8;              // 0..127
        int k = j & 255;
        float v;
        if (n < 64) v = mw0[n * 512 + k];
        else        v = mw0[(n - 64) * 512 + 256 + k];
        splith1(v, g_Wuvh[j], g_Wuvl[j]);
    }
}

// ===================== tensor-core fp16 2-term GEMM (templated tile) ========
// C(MxN) = A(MxK) @ B(KxN); A single fp16 plane, B fp16 hi/lo [N][K].
// Tile T x T, K-step 64, 256 threads (8 warps, 4 along m x 2 along n).
#define TSG 72            // padded k-stride in fp16 units

template <int T>
__global__ void __launch_bounds__(256, 1)
gemm_h_kernel(const __half* __restrict__ Ag,
              const __half* __restrict__ Bhig,
              const __half* __restrict__ Blog,
              float* __restrict__ C, int M, int N, int K) {
    constexpr int SA  = 0;
    constexpr int SBH = T * TSG;
    constexpr int SBL = 2 * T * TSG;
    constexpr int MT = T / 64;
    constexpr int NT = T / 16;
    constexpr int IT = T / 32;

    extern __shared__ __half sm[];
    int tid = threadIdx.x, w = tid >> 5, lane = tid & 31;
    int g = lane >> 2, t4 = lane & 3;
    int m0 = blockIdx.y * T, n0 = blockIdx.x * T;
    int mw = (w & 3) * (T / 4);
    int nw = (w >> 2) * (T / 2);

    float Cc[MT][NT][4];
#pragma unroll
    for (int mt = 0; mt < MT; mt++)
#pragma unroll
        for (int nt = 0; nt < NT; nt++)
#pragma unroll
            for (int q = 0; q < 4; q++) Cc[mt][nt][q] = 0.f;

    for (int k0 = 0; k0 < K; k0 += 64) {
        uint4 av[IT], bh[IT], bl[IT];
#pragma unroll
        for (int it = 0; it < IT; it++) {
            int u = tid + it * 256;
            int row = u >> 3;
            int kq = (u & 7) * 8;
            av[it] = *(const uint4*)(Ag + (m0 + row) * K + k0 + kq);
            bh[it] = *(const uint4*)(Bhig + (n0 + row) * K + k0 + kq);
            bl[it] = *(const uint4*)(Blog + (n0 + row) * K + k0 + kq);
        }
        __syncthreads();
#pragma unroll
        for (int it = 0; it < IT; it++) {
            int u = tid + it * 256;
            int row = u >> 3;
            int kq = (u & 7) * 8;
            int base = row * TSG + kq;
            *(uint4*)&sm[SA + base] = av[it];
            *(uint4*)&sm[SBH + base] = bh[it];
            *(uint4*)&sm[SBL + base] = bl[it];
        }
        __syncthreads();

#pragma unroll
        for (int kc = 0; kc < 4; kc++) {
            int kk = kc * 16 + 2 * t4;
            uint32_t A[MT][4];
#pragma unroll
            for (int mt = 0; mt < MT; mt++) {
                int r0 = mw + mt * 16 + g;
                int r1 = r0 + 8;
                A[mt][0] = *(const uint32_t*)&sm[SA + r0 * TSG + kk];
                A[mt][1] = *(const uint32_t*)&sm[SA + r1 * TSG + kk];
                A[mt][2] = *(const uint32_t*)&sm[SA + r0 * TSG + kk + 8];
                A[mt][3] = *(const uint32_t*)&sm[SA + r1 * TSG + kk + 8];
            }
#pragma unroll
            for (int nt = 0; nt < NT; nt++) {
                int nrow = nw + nt * 8 + g;
                uint32_t bh0 = *(const uint32_t*)&sm[SBH + nrow * TSG + kk];
                uint32_t bh1 = *(const uint32_t*)&sm[SBH + nrow * TSG + kk + 8];
                uint32_t bl0 = *(const uint32_t*)&sm[SBL + nrow * TSG + kk];
                uint32_t bl1 = *(const uint32_t*)&sm[SBL + nrow * TSG + kk + 8];
#pragma unroll
                for (int mt = 0; mt < MT; mt++) {
                    mmah(Cc[mt][nt], A[mt], bh0, bh1);
                    mmah(Cc[mt][nt], A[mt], bl0, bl1);
                }
            }
        }
    }

#pragma unroll
    for (int mt = 0; mt < MT; mt++) {
        int r0 = m0 + mw + mt * 16 + g;
        int r1 = r0 + 8;
#pragma unroll
        for (int nt = 0; nt < NT; nt++) {
            int col = n0 + nw + nt * 8 + 2 * t4;
            *(float2*)(C + r0 * N + col) = make_float2(Cc[mt][nt][0], Cc[mt][nt][1]);
            *(float2*)(C + r1 * N + col) = make_float2(Cc[mt][nt][2], Cc[mt][nt][3]);
        }
    }
}

#define GEMM_SMEM_BYTES_128 (3 * 128 * TSG * 2)
#define GEMM_SMEM_BYTES_64  (3 * 64 * TSG * 2)

// ===================== gather taps -> f (fp16, ILP 8) =======================
__global__ void gather_f_kernel(const float* __restrict__ cb0,
                                const float* __restrict__ cb1,
                                const float* __restrict__ cb2,
                                const float* __restrict__ cb3) {
    int t0 = blockIdx.x * 256 + threadIdx.x;   // 0..65535
#pragma unroll
    for (int q = 0; q < 8; q++) {
        int idx = t0 + q * 65536;
        int row = idx >> 8;        // (l,b): 0..2047
        int m = idx & 255;
        int l = row >> 4, b = row & 15;
        int br = m >> 6, c = m & 63;
        int k, pad, base;
        const float* cb;
        if (br == 0)      { k = 1; base = 0; cb = cb0; }
        else if (br == 1) { k = 3; base = 1; cb = cb1; }
        else if (br == 2) { k = 5; base = 4; cb = cb2; }
        else              { k = 7; base = 9; cb = cb3; }
        pad = (k - 1) >> 1;
        float sum = cb[c];
        for (int tt = 0; tt < k; tt++) {
            int l2 = l - pad + tt;
            if ((unsigned)l2 < (unsigned)LL)
                sum += g_G[(l2 * BB + b) * GCOLS + (base + tt) * 64 + c];
        }
        g_ff[idx] = __float2half_rn(lrelu(sum));
    }
}

// ===================== pair kernel (round-9, unchanged) =====================
// grid (16, 16): blockIdx.x -> j-tile of 8, blockIdx.y -> b. 128 threads.
#define PV_STRIDE 132
#define P_W4   0
#define P_V    49152
#define P_U    82944
#define P_B    84992
#define P_RED  86016
#define P_SR   87040
#define P_TR   89088
#define PAIR_SMEM_BYTES 91136

__global__ void __launch_bounds__(128, 2)
pair_mma_kernel(const float* __restrict__ uv,
                const float* __restrict__ mw1, const float* __restrict__ mw2,
                const float* __restrict__ mw3,
                const float* __restrict__ mb0, const float* __restrict__ mb1,
                const float* __restrict__ mb2, const float* __restrict__ mb3,
                const float* __restrict__ lw0, const float* __restrict__ lb0,
                const float* __restrict__ lw1, const float* __restrict__ lb1,
                float* __restrict__ out) {
    extern __shared__ char smp[];
    int tid = threadIdx.x, w = tid >> 5, lane = tid & 31;
    int g = lane >> 2, t4 = lane & 3;
    int b = blockIdx.y, j0 = blockIdx.x * 8;

    // ---- stage weights as packed uint4 fragments (fp16 hi/lo) ----
    {
        uint4* W4 = (uint4*)(smp + P_W4);
        for (int e = tid; e < 3072; e += 128) {
            int t4i = e & 3;
            int n = (e >> 2) & 63;
            int kc = (e >> 8) & 3;
            int l = e >> 10;
            const float* wsrc = (l == 0) ? mw1 : (l == 1) ? mw2 : mw3;
            int k0 = kc * 16 + 2 * t4i;
            float2 v01 = *(const float2*)(wsrc + n * 64 + k0);
            float2 v89 = *(const float2*)(wsrc + n * 64 + k0 + 8);
            uint32_t h0, l0, h1, l1;
            splith2(v01.x, v01.y, h0, l0);
            splith2(v89.x, v89.y, h1, l1);
            uint4 pk; pk.x = h0; pk.y = h1; pk.z = l0; pk.w = l1;
            W4[e] = pk;
        }
    }
    // ---- stage V[k][i] (f32, stride 132) ----
    {
        float* V = (float*)(smp + P_V);
        const float* vp = uv + (tid * BB + b) * 128 + 64;
#pragma unroll
        for (int q = 0; q < 16; q++) {
            float4 v4 = *(const float4*)(vp + q * 4);
            V[(q * 4 + 0) * PV_STRIDE + tid] = v4.x;
            V[(q * 4 + 1) * PV_STRIDE + tid] = v4.y;
            V[(q * 4 + 2) * PV_STRIDE + tid] = v4.z;
            V[(q * 4 + 3) * PV_STRIDE + tid] = v4.w;
        }
    }
    if (tid < 64) {
        float* U = (float*)(smp + P_U);
#pragma unroll
        for (int jt = 0; jt < 8; jt++)
            U[jt * 64 + tid] = uv[((j0 + jt) * BB + b) * 128 + tid];
        float* Bs = (float*)(smp + P_B);
        Bs[tid] = mb0[tid];
        Bs[64 + tid] = mb1[tid];
        Bs[128 + tid] = mb2[tid];
        Bs[192 + tid] = mb3[tid];
    }
    __syncthreads();

    const float* V = (const float*)(smp + P_V);
    const float* U = (const float*)(smp + P_U);
    const float* BIAS = (const float*)(smp + P_B);
    const uint4* W4 = (const uint4*)(smp + P_W4);
    float* RED = (float*)(smp + P_RED);
    float* SR = (float*)(smp + P_SR);

    for (int jt = 0; jt < 8; jt++) {
        uint32_t A[2][4][4];

        // ---- layer-1 A fragments: x = lrelu(u + v + b0), single fp16 ----
#pragma unroll
        for (int mt = 0; mt < 2; mt++) {
            int r0 = w * 32 + mt * 16 + g;
            int r1 = r0 + 8;
#pragma unroll
            for (int kc = 0; kc < 4; kc++) {
                int k0 = kc * 16 + 2 * t4;
                float ub0 = U[jt * 64 + k0]     + BIAS[k0];
                float ub1 = U[jt * 64 + k0 + 1] + BIAS[k0 + 1];
                float ub8 = U[jt * 64 + k0 + 8] + BIAS[k0 + 8];
                float ub9 = U[jt * 64 + k0 + 9] + BIAS[k0 + 9];
                float x00 = lrelu(ub0 + V[k0 * PV_STRIDE + r0]);
                float x01 = lrelu(ub1 + V[(k0 + 1) * PV_STRIDE + r0]);
                float x10 = lrelu(ub0 + V[k0 * PV_STRIDE + r1]);
                float x11 = lrelu(ub1 + V[(k0 + 1) * PV_STRIDE + r1]);
                float x08 = lrelu(ub8 + V[(k0 + 8) * PV_STRIDE + r0]);
                float x09 = lrelu(ub9 + V[(k0 + 9) * PV_STRIDE + r0]);
                float x18 = lrelu(ub8 + V[(k0 + 8) * PV_STRIDE + r1]);
                float x19 = lrelu(ub9 + V[(k0 + 9) * PV_STRIDE + r1]);
                A[mt][kc][0] = packh2(x00, x01);
                A[mt][kc][1] = packh2(x10, x11);
                A[mt][kc][2] = packh2(x08, x09);
                A[mt][kc][3] = packh2(x18, x19);
            }
        }

        // ---- 3 chained MMA layers (2-term: A*Wh + A*Wl) ----
        float Cc[2][8][4];
#pragma unroll
        for (int l = 0; l < 3; l++) {
#pragma unroll
            for (int mt = 0; mt < 2; mt++)
#pragma unroll
                for (int nt = 0; nt < 8; nt++)
#pragma unroll
                    for (int q = 0; q < 4; q++) Cc[mt][nt][q] = 0.f;

#pragma unroll
            for (int kc = 0; kc < 4; kc++) {
#pragma unroll
                for (int nt = 0; nt < 8; nt++) {
                    uint4 wq = W4[((l * 4 + kc) * 64 + nt * 8 + g) * 4 + t4];
                    mmah(Cc[0][nt], A[0][kc], wq.x, wq.y);
                    mmah(Cc[1][nt], A[1][kc], wq.x, wq.y);
                    mmah(Cc[0][nt], A[0][kc], wq.z, wq.w);
                    mmah(Cc[1][nt], A[1][kc], wq.z, wq.w);
                }
            }

            if (l < 2) {
                const float* bl = BIAS + 64 * (l + 1);
#pragma unroll
                for (int nt = 0; nt < 8; nt++) {
                    int col = nt * 8 + 2 * t4;
                    float bx = bl[col], by = bl[col + 1];
                    int kc2 = nt >> 1, ri = (nt & 1) * 2;
#pragma unroll
                    for (int mt = 0; mt < 2; mt++) {
                        float h0 = lrelu(Cc[mt][nt][0] + bx);
                        float h1 = lrelu(Cc[mt][nt][1] + by);
                        float h2 = lrelu(Cc[mt][nt][2] + bx);
                        float h3 = lrelu(Cc[mt][nt][3] + by);
                        A[mt][kc2][ri]     = packh2(h0, h1);
                        A[mt][kc2][ri + 1] = packh2(h2, h3);
                    }
                }
            }
        }

        // ---- final: bias + lrelu, reduce over i ----
        {
            const float* bl = BIAS + 192;
#pragma unroll
            for (int nt = 0; nt < 8; nt++) {
                int col = nt * 8 + 2 * t4;
                float bx = bl[col], by = bl[col + 1];
                float s0 = lrelu(Cc[0][nt][0] + bx) + lrelu(Cc[0][nt][2] + bx) +
                           lrelu(Cc[1][nt][0] + bx) + lrelu(Cc[1][nt][2] + bx);
                float s1 = lrelu(Cc[0][nt][1] + by) + lrelu(Cc[0][nt][3] + by) +
                           lrelu(Cc[1][nt][1] + by) + lrelu(Cc[1][nt][3] + by);
                s0 += __shfl_xor_sync(0xffffffffu, s0, 4);
                s0 += __shfl_xor_sync(0xffffffffu, s0, 8);
                s0 += __shfl_xor_sync(0xffffffffu, s0, 16);
                s1 += __shfl_xor_sync(0xffffffffu, s1, 4);
                s1 += __shfl_xor_sync(0xffffffffu, s1, 8);
                s1 += __shfl_xor_sync(0xffffffffu, s1, 16);
                if (lane < 4) {
                    RED[w * 64 + col] = s0;
                    RED[w * 64 + col + 1] = s1;
                }
            }
        }
        __syncthreads();
        if (tid < 64) {
            float s = RED[tid] + RED[64 + tid] + RED[128 + tid] + RED[192 + tid];
            SR[jt * 64 + tid] = s;
        }
        __syncthreads();
    }

    // ---- fused head: t = lrelu(s@lw0.T+lb0); out = lrelu(t@lw1.T+lb1) ----
    float* TR = (float*)(smp + P_TR);
#pragma unroll
    for (int q = 0; q < 4; q++) {
        int idx = tid + 128 * q;
        int jt = idx >> 6, o = idx & 63;
        const float* wr = lw0 + o * 64;
        float acc = lb0[o];
#pragma unroll
        for (int c = 0; c < 64; c += 4) {
            float4 w4 = *(const float4*)(wr + c);
            acc += SR[jt * 64 + c] * w4.x + SR[jt * 64 + c + 1] * w4.y +
                   SR[jt * 64 + c + 2] * w4.z + SR[jt * 64 + c + 3] * w4.w;
        }
        TR[idx] = lrelu(acc);
    }
    __syncthreads();
#pragma unroll
    for (int q = 0; q < 16; q++) {
        int idx = tid + 128 * q;
        int jt = idx >> 8, o = idx & 255;
        const float* wr = lw1 + o * 64;
        float acc = lb1[o];
#pragma unroll
        for (int c = 0; c < 64; c += 4) {
            float4 w4 = *(const float4*)(wr + c);
            acc += TR[jt * 64 + c] * w4.x + TR[jt * 64 + c + 1] * w4.y +
                   TR[jt * 64 + c + 2] * w4.z + TR[jt * 64 + c + 3] * w4.w;
        }
        out[((j0 + jt) * BB + b) * 256 + o] = lrelu(acc);
    }
}

// ===================== host launch ==========================================
extern "C" void kernel_launch(void* const* d_in, const int* in_sizes, int n_in,
                              void* d_out, int out_size) {
    const float* x   = (const float*)d_in[0];
    const float* cw0 = (const float*)d_in[1];
    const float* cb0 = (const float*)d_in[2];
    const float* cw1 = (const float*)d_in[3];
    const float* cb1 = (const float*)d_in[4];
    const float* cw2 = (const float*)d_in[5];
    const float* cb2 = (const float*)d_in[6];
    const float* cw3 = (const float*)d_in[7];
    const float* cb3 = (const float*)d_in[8];
    const float* mw0 = (const float*)d_in[9];
    const float* mb0 = (const float*)d_in[10];
    const float* mw1 = (const float*)d_in[11];
    const float* mb1 = (const float*)d_in[12];
    const float* mw2 = (const float*)d_in[13];
    const float* mb2 = (const float*)d_in[14];
    const float* mw3 = (const float*)d_in[15];
    const float* mb3 = (const float*)d_in[16];
    const float* lw0 = (const float*)d_in[17];
    const float* lb0 = (const float*)d_in[18];
    const float* lw1 = (const float*)d_in[19];
    const float* lb1 = (const float*)d_in[20];
    float* out = (float*)d_out;

    float *G, *uvb;
    __half *xf, *ff, *Wrh, *Wrl, *Wuvh, *Wuvl;
    cudaGetSymbolAddress((void**)&G, g_G);
    cudaGetSymbolAddress((void**)&uvb, g_uv);
    cudaGetSymbolAddress((void**)&xf, g_xf);
    cudaGetSymbolAddress((void**)&ff, g_ff);
    cudaGetSymbolAddress((void**)&Wrh, g_Wrh);
    cudaGetSymbolAddress((void**)&Wrl, g_Wrl);
    cudaGetSymbolAddress((void**)&Wuvh, g_Wuvh);
    cudaGetSymbolAddress((void**)&Wuvl, g_Wuvl);

    // 1) prep (x -> fp16, conv weights + Wuv -> fp16 hi/lo)
    prep_kernel<<<(NX + NW + NU + 255) / 256, 256>>>(x, cw0, cw1, cw2, cw3, mw0);

    cudaFuncSetAttribute(gemm_h_kernel<128>,
                         cudaFuncAttributeMaxDynamicSharedMemorySize,
                         GEMM_SMEM_BYTES_128);
    cudaFuncSetAttribute(gemm_h_kernel<64>,
                         cudaFuncAttributeMaxDynamicSharedMemorySize,
                         GEMM_SMEM_BYTES_64);

    // 2) conv as GEMM: G(2048x1024) = x(2048x512) @ Wr  (128x128 tiles)
    gemm_h_kernel<128><<<dim3(GCOLS / 128, ROWS / 128), 256,
                         GEMM_SMEM_BYTES_128>>>(
        xf, Wrh, Wrl, G, ROWS, GCOLS, EE);

    // 3) gather taps -> f (fp16)
    gather_f_kernel<<<256, 256>>>(cb0, cb1, cb2, cb3);

    // 4) uv(2048x128) = f(2048x256) @ Wuv  (64x64 tiles -> 64 CTAs)
    gemm_h_kernel<64><<<dim3(128 / 64, ROWS / 64), 256,
                        GEMM_SMEM_BYTES_64>>>(
        ff, Wuvh, Wuvl, uvb, ROWS, 128, MM);

    // 5) pair stage + fused head (fp16 2-term, round-6 structure)
    cudaFuncSetAttribute(pair_mma_kernel,
                         cudaFuncAttributeMaxDynamicSharedMemorySize,
                         PAIR_SMEM_BYTES);
    pair_mma_kernel<<<dim3(16, 16), 128, PAIR_SMEM_BYTES>>>(
        uvb, mw1, mw2, mw3, mb0, mb1, mb2, mb3,
        lw0, lb0, lw1, lb1, out);
}

// round 12
// speedup vs baseline: 2.0047x; 1.2366x over previous
#include <cuda_runtime.h>
#include <cuda_bf16.h>
#include <cuda_fp16.h>
#include <cstdint>

// ---------------------------------------------------------------------------
// RelationLayer: L=128, B=16, E=512, C=64, KERNELS={1,3,5,7}, M=256, OUT=256
//  1) prep: x -> fp16, conv weights -> fp16, Wuv -> fp16
//  2) G = x(2048x512) @ Wr               (pure fp16 GEMM, 128x128 tiles)
//  3) f = lrelu(gather taps + bias) -> fp16
//  4) uv = f(2048x256) @ Wuv(256x128)    (pure fp16 GEMM, 64x64 tiles)
//  5) pair kernel: round-6 structure, pure fp16 MMA (1 mma per tile term).
// ---------------------------------------------------------------------------

#define LL 128
#define BB 16
#define EE 512
#define MM 256
#define ROWS 2048
#define GCOLS 1024

#define NX (ROWS * EE)
#define NW (EE * GCOLS)
#define NU (128 * MM)
#define NF (ROWS * MM)

__device__ float g_G[ROWS * GCOLS];
__device__ float g_uv[ROWS * 128];
__device__ __half g_xf[NX];
__device__ __half g_ff[NF];
__device__ __half g_Wrh[NW];
__device__ __half g_Wuvh[NU];

// ===================== helpers ==============================================
__device__ __forceinline__ float lrelu(float x) { return fmaxf(x, 0.1f * x); }

// pack two f32 into one fp16x2 word (low 16 bits = first element)
__device__ __forceinline__ uint32_t packh2(float a, float b) {
    __half2 h = __floats2half2_rn(a, b);
    return *(uint32_t*)&h;
}

// mma.sync m16n8k16 fp16 -> f32 accumulate (baseline PTX)
__device__ __forceinline__ void mmah(float c[4], const uint32_t a[4],
                                     uint32_t b0, uint32_t b1) {
    asm volatile(
        "mma.sync.aligned.m16n8k16.row.col.f32.f16.f16.f32 "
        "{%0,%1,%2,%3}, {%4,%5,%6,%7}, {%8,%9}, {%0,%1,%2,%3};"
        : "+f"(c[0]), "+f"(c[1]), "+f"(c[2]), "+f"(c[3])
        : "r"(a[0]), "r"(a[1]), "r"(a[2]), "r"(a[3]), "r"(b0), "r"(b1));
}

// ===================== prep: x/Wr/Wuv -> fp16 ===============================
__global__ void prep_kernel(const float* __restrict__ x,
                            const float* __restrict__ cw0,
                            const float* __restrict__ cw1,
                            const float* __restrict__ cw2,
                            const float* __restrict__ cw3,
                            const float* __restrict__ mw0) {
    int idx = blockIdx.x * 256 + threadIdx.x;
    if (idx < NX) {
        g_xf[idx] = __float2half_rn(x[idx]);
    } else if (idx < NX + NW) {
        int j = idx - NX;
        int col = j >> 9;            // n: 0..1023
        int e = j & 511;             // k
        int p = col >> 6;
        int c = col & 63;
        const float* w; int k, t;
        if (p < 1)      { w = cw0; k = 1; t = p; }
        else if (p < 4) { w = cw1; k = 3; t = p - 1; }
        else if (p < 9) { w = cw2; k = 5; t = p - 4; }
        else            { w = cw3; k = 7; t = p - 9; }
        g_Wrh[j] = __float2half_rn(w[(c * k + t) * EE + e]);
    } else if (idx < NX + NW + NU) {
        int j = idx - NX - NW;
        int n = j >> 8;              // 0..127
        int k = j & 255;
        float v;
        if (n < 64) v = mw0[n * 512 + k];
        else        v = mw0[(n - 64) * 512 + 256 + k];
        g_Wuvh[j] = __float2half_rn(v);
    }
}

// ===================== pure fp16 GEMM (templated tile) ======================
// C(MxN) = A(MxK) @ B(KxN); A and B single fp16 planes, B as [N][K].
// Tile T x T, K-step 64, 256 threads (8 warps, 4 along m x 2 along n).
#define TSG 72            // padded k-stride in fp16 units

template <int T>
__global__ void __launch_bounds__(256, 1)
gemm_h_kernel(const __half* __restrict__ Ag,
              const __half* __restrict__ Bg,
              float* __restrict__ C, int M, int N, int K) {
    constexpr int SA = 0;
    constexpr int SB = T * TSG;
    constexpr int MT = T / 64;
    constexpr int NT = T / 16;
    constexpr int IT = T / 32;

    extern __shared__ __half sm[];
    int tid = threadIdx.x, w = tid >> 5, lane = tid & 31;
    int g = lane >> 2, t4 = lane & 3;
    int m0 = blockIdx.y * T, n0 = blockIdx.x * T;
    int mw = (w & 3) * (T / 4);
    int nw = (w >> 2) * (T / 2);

    float Cc[MT][NT][4];
#pragma unroll
    for (int mt = 0; mt < MT; mt++)
#pragma unroll
        for (int nt = 0; nt < NT; nt++)
#pragma unroll
            for (int q = 0; q < 4; q++) Cc[mt][nt][q] = 0.f;

    for (int k0 = 0; k0 < K; k0 += 64) {
        uint4 av[IT], bv[IT];
#pragma unroll
        for (int it = 0; it < IT; it++) {
            int u = tid + it * 256;
            int row = u >> 3;
            int kq = (u & 7) * 8;
            av[it] = *(const uint4*)(Ag + (m0 + row) * K + k0 + kq);
            bv[it] = *(const uint4*)(Bg + (n0 + row) * K + k0 + kq);
        }
        __syncthreads();
#pragma unroll
        for (int it = 0; it < IT; it++) {
            int u = tid + it * 256;
            int row = u >> 3;
            int kq = (u & 7) * 8;
            int base = row * TSG + kq;
            *(uint4*)&sm[SA + base] = av[it];
            *(uint4*)&sm[SB + base] = bv[it];
        }
        __syncthreads();

#pragma unroll
        for (int kc = 0; kc < 4; kc++) {
            int kk = kc * 16 + 2 * t4;
            uint32_t A[MT][4];
#pragma unroll
            for (int mt = 0; mt < MT; mt++) {
                int r0 = mw + mt * 16 + g;
                int r1 = r0 + 8;
                A[mt][0] = *(const uint32_t*)&sm[SA + r0 * TSG + kk];
                A[mt][1] = *(const uint32_t*)&sm[SA + r1 * TSG + kk];
                A[mt][2] = *(const uint32_t*)&sm[SA + r0 * TSG + kk + 8];
                A[mt][3] = *(const uint32_t*)&sm[SA + r1 * TSG + kk + 8];
            }
#pragma unroll
            for (int nt = 0; nt < NT; nt++) {
                int nrow = nw + nt * 8 + g;
                uint32_t b0 = *(const uint32_t*)&sm[SB + nrow * TSG + kk];
                uint32_t b1 = *(const uint32_t*)&sm[SB + nrow * TSG + kk + 8];
#pragma unroll
                for (int mt = 0; mt < MT; mt++)
                    mmah(Cc[mt][nt], A[mt], b0, b1);
            }
        }
    }

#pragma unroll
    for (int mt = 0; mt < MT; mt++) {
        int r0 = m0 + mw + mt * 16 + g;
        int r1 = r0 + 8;
#pragma unroll
        for (int nt = 0; nt < NT; nt++) {
            int col = n0 + nw + nt * 8 + 2 * t4;
            *(float2*)(C + r0 * N + col) = make_float2(Cc[mt][nt][0], Cc[mt][nt][1]);
            *(float2*)(C + r1 * N + col) = make_float2(Cc[mt][nt][2], Cc[mt][nt][3]);
        }
    }
}

#define GEMM_SMEM_BYTES_128 (2 * 128 * TSG * 2)
#define GEMM_SMEM_BYTES_64  (2 * 64 * TSG * 2)

// ===================== gather taps -> f (fp16, ILP 8) =======================
__global__ void gather_f_kernel(const float* __restrict__ cb0,
                                const float* __restrict__ cb1,
                                const float* __restrict__ cb2,
                                const float* __restrict__ cb3) {
    int t0 = blockIdx.x * 256 + threadIdx.x;   // 0..65535
#pragma unroll
    for (int q = 0; q < 8; q++) {
        int idx = t0 + q * 65536;
        int row = idx >> 8;        // (l,b): 0..2047
        int m = idx & 255;
        int l = row >> 4, b = row & 15;
        int br = m >> 6, c = m & 63;
        int k, pad, base;
        const float* cb;
        if (br == 0)      { k = 1; base = 0; cb = cb0; }
        else if (br == 1) { k = 3; base = 1; cb = cb1; }
        else if (br == 2) { k = 5; base = 4; cb = cb2; }
        else              { k = 7; base = 9; cb = cb3; }
        pad = (k - 1) >> 1;
        float sum = cb[c];
        for (int tt = 0; tt < k; tt++) {
            int l2 = l - pad + tt;
            if ((unsigned)l2 < (unsigned)LL)
                sum += g_G[(l2 * BB + b) * GCOLS + (base + tt) * 64 + c];
        }
        g_ff[idx] = __float2half_rn(lrelu(sum));
    }
}

// ===================== pair kernel (round-6 structure, pure fp16 MMA) =======
// grid (16, 16): blockIdx.x -> j-tile of 8, blockIdx.y -> b. 128 threads.
// Warp w handles i-rows [w*32, w*32+32) as 2 m-tiles of 16.
// Weights staged as packed uint2 fragments (single fp16):
//   W2[l][kc][n][t4] = {w_b0, w_b1} (8B per entry), 3072 entries = 24576 B
// Activations: single fp16 fragments (D = A*W -> 2 mma per (kc,nt)).
#define PV_STRIDE 132
#define P_W2   0
#define P_V    24576
#define P_U    58368
#define P_B    60416
#define P_RED  61440
#define P_SR   62464
#define P_TR   64512
#define PAIR_SMEM_BYTES 66560

__global__ void __launch_bounds__(128, 2)
pair_mma_kernel(const float* __restrict__ uv,
                const float* __restrict__ mw1, const float* __restrict__ mw2,
                const float* __restrict__ mw3,
                const float* __restrict__ mb0, const float* __restrict__ mb1,
                const float* __restrict__ mb2, const float* __restrict__ mb3,
                const float* __restrict__ lw0, const float* __restrict__ lb0,
                const float* __restrict__ lw1, const float* __restrict__ lb1,
                float* __restrict__ out) {
    extern __shared__ char smp[];
    int tid = threadIdx.x, w = tid >> 5, lane = tid & 31;
    int g = lane >> 2, t4 = lane & 3;
    int b = blockIdx.y, j0 = blockIdx.x * 8;

    // ---- stage weights as packed uint2 fragments (single fp16) ----
    {
        uint2* W2 = (uint2*)(smp + P_W2);
        for (int e = tid; e < 3072; e += 128) {
            int t4i = e & 3;
            int n = (e >> 2) & 63;
            int kc = (e >> 8) & 3;
            int l = e >> 10;
            const float* wsrc = (l == 0) ? mw1 : (l == 1) ? mw2 : mw3;
            int k0 = kc * 16 + 2 * t4i;
            float2 v01 = *(const float2*)(wsrc + n * 64 + k0);
            float2 v89 = *(const float2*)(wsrc + n * 64 + k0 + 8);
            uint2 pk;
            pk.x = packh2(v01.x, v01.y);
            pk.y = packh2(v89.x, v89.y);
            W2[e] = pk;
        }
    }
    // ---- stage V[k][i] (f32, stride 132) ----
    {
        float* V = (float*)(smp + P_V);
        const float* vp = uv + (tid * BB + b) * 128 + 64;
#pragma unroll
        for (int q = 0; q < 16; q++) {
            float4 v4 = *(const float4*)(vp + q * 4);
            V[(q * 4 + 0) * PV_STRIDE + tid] = v4.x;
            V[(q * 4 + 1) * PV_STRIDE + tid] = v4.y;
            V[(q * 4 + 2) * PV_STRIDE + tid] = v4.z;
            V[(q * 4 + 3) * PV_STRIDE + tid] = v4.w;
        }
    }
    if (tid < 64) {
        float* U = (float*)(smp + P_U);
#pragma unroll
        for (int jt = 0; jt < 8; jt++)
            U[jt * 64 + tid] = uv[((j0 + jt) * BB + b) * 128 + tid];
        float* Bs = (float*)(smp + P_B);
        Bs[tid] = mb0[tid];
        Bs[64 + tid] = mb1[tid];
        Bs[128 + tid] = mb2[tid];
        Bs[192 + tid] = mb3[tid];
    }
    __syncthreads();

    const float* V = (const float*)(smp + P_V);
    const float* U = (const float*)(smp + P_U);
    const float* BIAS = (const float*)(smp + P_B);
    const uint2* W2 = (const uint2*)(smp + P_W2);
    float* RED = (float*)(smp + P_RED);
    float* SR = (float*)(smp + P_SR);

    for (int jt = 0; jt < 8; jt++) {
        uint32_t A[2][4][4];

        // ---- layer-1 A fragments: x = lrelu(u + v + b0), single fp16 ----
#pragma unroll
        for (int mt = 0; mt < 2; mt++) {
            int r0 = w * 32 + mt * 16 + g;
            int r1 = r0 + 8;
#pragma unroll
            for (int kc = 0; kc < 4; kc++) {
                int k0 = kc * 16 + 2 * t4;
                float ub0 = U[jt * 64 + k0]     + BIAS[k0];
                float ub1 = U[jt * 64 + k0 + 1] + BIAS[k0 + 1];
                float ub8 = U[jt * 64 + k0 + 8] + BIAS[k0 + 8];
                float ub9 = U[jt * 64 + k0 + 9] + BIAS[k0 + 9];
                float x00 = lrelu(ub0 + V[k0 * PV_STRIDE + r0]);
                float x01 = lrelu(ub1 + V[(k0 + 1) * PV_STRIDE + r0]);
                float x10 = lrelu(ub0 + V[k0 * PV_STRIDE + r1]);
                float x11 = lrelu(ub1 + V[(k0 + 1) * PV_STRIDE + r1]);
                float x08 = lrelu(ub8 + V[(k0 + 8) * PV_STRIDE + r0]);
                float x09 = lrelu(ub9 + V[(k0 + 9) * PV_STRIDE + r0]);
                float x18 = lrelu(ub8 + V[(k0 + 8) * PV_STRIDE + r1]);
                float x19 = lrelu(ub9 + V[(k0 + 9) * PV_STRIDE + r1]);
                A[mt][kc][0] = packh2(x00, x01);
                A[mt][kc][1] = packh2(x10, x11);
                A[mt][kc][2] = packh2(x08, x09);
                A[mt][kc][3] = packh2(x18, x19);
            }
        }

        // ---- 3 chained MMA layers (single-term: A*W) ----
        float Cc[2][8][4];
#pragma unroll
        for (int l = 0; l < 3; l++) {
#pragma unroll
            for (int mt = 0; mt < 2; mt++)
#pragma unroll
                for (int nt = 0; nt < 8; nt++)
#pragma unroll
                    for (int q = 0; q < 4; q++) Cc[mt][nt][q] = 0.f;

#pragma unroll
            for (int kc = 0; kc < 4; kc++) {
#pragma unroll
                for (int nt = 0; nt < 8; nt++) {
                    uint2 wq = W2[((l * 4 + kc) * 64 + nt * 8 + g) * 4 + t4];
                    mmah(Cc[0][nt], A[0][kc], wq.x, wq.y);
                    mmah(Cc[1][nt], A[1][kc], wq.x, wq.y);
                }
            }

            if (l < 2) {
                const float* bl = BIAS + 64 * (l + 1);
#pragma unroll
                for (int nt = 0; nt < 8; nt++) {
                    int col = nt * 8 + 2 * t4;
                    float bx = bl[col], by = bl[col + 1];
                    int kc2 = nt >> 1, ri = (nt & 1) * 2;
#pragma unroll
                    for (int mt = 0; mt < 2; mt++) {
                        float h0 = lrelu(Cc[mt][nt][0] + bx);
                        float h1 = lrelu(Cc[mt][nt][1] + by);
                        float h2 = lrelu(Cc[mt][nt][2] + bx);
                        float h3 = lrelu(Cc[mt][nt][3] + by);
                        A[mt][kc2][ri]     = packh2(h0, h1);
                        A[mt][kc2][ri + 1] = packh2(h2, h3);
                    }
                }
            }
        }

        // ---- final: bias + lrelu, reduce over i ----
        {
            const float* bl = BIAS + 192;
#pragma unroll
            for (int nt = 0; nt < 8; nt++) {
                int col = nt * 8 + 2 * t4;
                float bx = bl[col], by = bl[col + 1];
                float s0 = lrelu(Cc[0][nt][0] + bx) + lrelu(Cc[0][nt][2] + bx) +
                           lrelu(Cc[1][nt][0] + bx) + lrelu(Cc[1][nt][2] + bx);
                float s1 = lrelu(Cc[0][nt][1] + by) + lrelu(Cc[0][nt][3] + by) +
                           lrelu(Cc[1][nt][1] + by) + lrelu(Cc[1][nt][3] + by);
                s0 += __shfl_xor_sync(0xffffffffu, s0, 4);
                s0 += __shfl_xor_sync(0xffffffffu, s0, 8);
                s0 += __shfl_xor_sync(0xffffffffu, s0, 16);
                s1 += __shfl_xor_sync(0xffffffffu, s1, 4);
                s1 += __shfl_xor_sync(0xffffffffu, s1, 8);
                s1 += __shfl_xor_sync(0xffffffffu, s1, 16);
                if (lane < 4) {
                    RED[w * 64 + col] = s0;
                    RED[w * 64 + col + 1] = s1;
                }
            }
        }
        __syncthreads();
        if (tid < 64) {
            float s = RED[tid] + RED[64 + tid] + RED[128 + tid] + RED[192 + tid];
            SR[jt * 64 + tid] = s;
        }
        __syncthreads();
    }

    // ---- fused head: t = lrelu(s@lw0.T+lb0); out = lrelu(t@lw1.T+lb1) ----
    float* TR = (float*)(smp + P_TR);
#pragma unroll
    for (int q = 0; q < 4; q++) {
        int idx = tid + 128 * q;
        int jt = idx >> 6, o = idx & 63;
        const float* wr = lw0 + o * 64;
        float acc = lb0[o];
#pragma unroll
        for (int c = 0; c < 64; c += 4) {
            float4 w4 = *(const float4*)(wr + c);
            acc += SR[jt * 64 + c] * w4.x + SR[jt * 64 + c + 1] * w4.y +
                   SR[jt * 64 + c + 2] * w4.z + SR[jt * 64 + c + 3] * w4.w;
        }
        TR[idx] = lrelu(acc);
    }
    __syncthreads();
#pragma unroll
    for (int q = 0; q < 16; q++) {
        int idx = tid + 128 * q;
        int jt = idx >> 8, o = idx & 255;
        const float* wr = lw1 + o * 64;
        float acc = lb1[o];
#pragma unroll
        for (int c = 0; c < 64; c += 4) {
            float4 w4 = *(const float4*)(wr + c);
            acc += TR[jt * 64 + c] * w4.x + TR[jt * 64 + c + 1] * w4.y +
                   TR[jt * 64 + c + 2] * w4.z + TR[jt * 64 + c + 3] * w4.w;
        }
        out[((j0 + jt) * BB + b) * 256 + o] = lrelu(acc);
    }
}

// ===================== host launch ==========================================
extern "C" void kernel_launch(void* const* d_in, const int* in_sizes, int n_in,
                              void* d_out, int out_size) {
    const float* x   = (const float*)d_in[0];
    const float* cw0 = (const float*)d_in[1];
    const float* cb0 = (const float*)d_in[2];
    const float* cw1 = (const float*)d_in[3];
    const float* cb1 = (const float*)d_in[4];
    const float* cw2 = (const float*)d_in[5];
    const float* cb2 = (const float*)d_in[6];
    const float* cw3 = (const float*)d_in[7];
    const float* cb3 = (const float*)d_in[8];
    const float* mw0 = (const float*)d_in[9];
    const float* mb0 = (const float*)d_in[10];
    const float* mw1 = (const float*)d_in[11];
    const float* mb1 = (const float*)d_in[12];
    const float* mw2 = (const float*)d_in[13];
    const float* mb2 = (const float*)d_in[14];
    const float* mw3 = (const float*)d_in[15];
    const float* mb3 = (const float*)d_in[16];
    const float* lw0 = (const float*)d_in[17];
    const float* lb0 = (const float*)d_in[18];
    const float* lw1 = (const float*)d_in[19];
    const float* lb1 = (const float*)d_in[20];
    float* out = (float*)d_out;

    float *G, *uvb;
    __half *xf, *ff, *Wrh, *Wuvh;
    cudaGetSymbolAddress((void**)&G, g_G);
    cudaGetSymbolAddress((void**)&uvb, g_uv);
    cudaGetSymbolAddress((void**)&xf, g_xf);
    cudaGetSymbolAddress((void**)&ff, g_ff);
    cudaGetSymbolAddress((void**)&Wrh, g_Wrh);
    cudaGetSymbolAddress((void**)&Wuvh, g_Wuvh);

    // 1) prep (x, conv weights, Wuv -> fp16)
    prep_kernel<<<(NX + NW + NU + 255) / 256, 256>>>(x, cw0, cw1, cw2, cw3, mw0);

    cudaFuncSetAttribute(gemm_h_kernel<128>,
                         cudaFuncAttributeMaxDynamicSharedMemorySize,
                         GEMM_SMEM_BYTES_128);
    cudaFuncSetAttribute(gemm_h_kernel<64>,
                         cudaFuncAttributeMaxDynamicSharedMemorySize,
                         GEMM_SMEM_BYTES_64);

    // 2) conv as GEMM: G(2048x1024) = x(2048x512) @ Wr  (128x128 tiles)
    gemm_h_kernel<128><<<dim3(GCOLS / 128, ROWS / 128), 256,
                         GEMM_SMEM_BYTES_128>>>(
        xf, Wrh, G, ROWS, GCOLS, EE);

    // 3) gather taps -> f (fp16)
    gather_f_kernel<<<256, 256>>>(cb0, cb1, cb2, cb3);

    // 4) uv(2048x128) = f(2048x256) @ Wuv  (64x64 tiles -> 64 CTAs)
    gemm_h_kernel<64><<<dim3(128 / 64, ROWS / 64), 256,
                        GEMM_SMEM_BYTES_64>>>(
        ff, Wuvh, uvb, ROWS, 128, MM);

    // 5) pair stage + fused head (pure fp16, round-6 structure)
    cudaFuncSetAttribute(pair_mma_kernel,
                         cudaFuncAttributeMaxDynamicSharedMemorySize,
                         PAIR_SMEM_BYTES);
    pair_mma_kernel<<<dim3(16, 16), 128, PAIR_SMEM_BYTES>>>(
        uvb, mw1, mw2, mw3, mb0, mb1, mb2, mb3,
        lw0, lb0, lw1, lb1, out);
}

// round 13
// speedup vs baseline: 2.0220x; 1.0086x over previous
#include <cuda_runtime.h>
#include <cuda_bf16.h>
#include <cuda_fp16.h>
#include <cstdint>

// ---------------------------------------------------------------------------
// RelationLayer: L=128, B=16, E=512, C=64, KERNELS={1,3,5,7}, M=256, OUT=256
//  1) prep: conv weights -> fp16, Wuv -> fp16 (weights only)
//  2) G = x(2048x512) @ Wr    (fp16 GEMM, x converted inline, G stored fp16)
//  3) f = lrelu(gather taps + bias) -> fp16
//  4) uv = f(2048x256) @ Wuv(256x128)  (full-K single-phase fp16 GEMM)
//  5) pair kernel: round-6 structure, pure fp16 MMA (unchanged from R12).
// ---------------------------------------------------------------------------

#define LL 128
#define BB 16
#define EE 512
#define MM 256
#define ROWS 2048
#define GCOLS 1024

#define NW (EE * GCOLS)
#define NU (128 * MM)
#define NF (ROWS * MM)

__device__ __half g_Gh[ROWS * GCOLS];
__device__ float g_uv[ROWS * 128];
__device__ __half g_ff[NF];
__device__ __half g_Wrh[NW];
__device__ __half g_Wuvh[NU];

// ===================== helpers ==============================================
__device__ __forceinline__ float lrelu(float x) { return fmaxf(x, 0.1f * x); }

// pack two f32 into one fp16x2 word (low 16 bits = first element)
__device__ __forceinline__ uint32_t packh2(float a, float b) {
    __half2 h = __floats2half2_rn(a, b);
    return *(uint32_t*)&h;
}

// mma.sync m16n8k16 fp16 -> f32 accumulate (baseline PTX)
__device__ __forceinline__ void mmah(float c[4], const uint32_t a[4],
                                     uint32_t b0, uint32_t b1) {
    asm volatile(
        "mma.sync.aligned.m16n8k16.row.col.f32.f16.f16.f32 "
        "{%0,%1,%2,%3}, {%4,%5,%6,%7}, {%8,%9}, {%0,%1,%2,%3};"
        : "+f"(c[0]), "+f"(c[1]), "+f"(c[2]), "+f"(c[3])
        : "r"(a[0]), "r"(a[1]), "r"(a[2]), "r"(a[3]), "r"(b0), "r"(b1));
}

// ===================== prep: Wr/Wuv -> fp16 (weights only) ==================
__global__ void prep_kernel(const float* __restrict__ cw0,
                            const float* __restrict__ cw1,
                            const float* __restrict__ cw2,
                            const float* __restrict__ cw3,
                            const float* __restrict__ mw0) {
    int idx = blockIdx.x * 256 + threadIdx.x;
    if (idx < NW) {
        int col = idx >> 9;          // n: 0..1023
        int e = idx & 511;           // k
        int p = col >> 6;
        int c = col & 63;
        const float* w; int k, t;
        if (p < 1)      { w = cw0; k = 1; t = p; }
        else if (p < 4) { w = cw1; k = 3; t = p - 1; }
        else if (p < 9) { w = cw2; k = 5; t = p - 4; }
        else            { w = cw3; k = 7; t = p - 9; }
        g_Wrh[idx] = __float2half_rn(w[(c * k + t) * EE + e]);
    } else if (idx < NW + NU) {
        int j = idx - NW;
        int n = j >> 8;              // 0..127
        int k = j & 255;
        float v;
        if (n < 64) v = mw0[n * 512 + k];
        else        v = mw0[(n - 64) * 512 + 256 + k];
        g_Wuvh[j] = __float2half_rn(v);
    }
}

// ===================== conv GEMM: x(f32, inline cvt) @ Wr -> G(fp16) ========
// 128x128 tile, K-step 64, 256 threads. M=2048, N=1024, K=512.
#define TSG 72            // padded k-stride in fp16 units

__global__ void __launch_bounds__(256, 1)
gemm_conv_kernel(const float* __restrict__ X,
                 const __half* __restrict__ Bg,
                 __half* __restrict__ Gh) {
    const int N = GCOLS, K = EE;
    constexpr int SA = 0;
    constexpr int SB = 128 * TSG;

    extern __shared__ __half sm[];
    int tid = threadIdx.x, w = tid >> 5, lane = tid & 31;
    int g = lane >> 2, t4 = lane & 3;
    int m0 = blockIdx.y * 128, n0 = blockIdx.x * 128;
    int mw = (w & 3) * 32;
    int nw = (w >> 2) * 64;

    float Cc[2][8][4];
#pragma unroll
    for (int mt = 0; mt < 2; mt++)
#pragma unroll
        for (int nt = 0; nt < 8; nt++)
#pragma unroll
            for (int q = 0; q < 4; q++) Cc[mt][nt][q] = 0.f;

    for (int k0 = 0; k0 < K; k0 += 64) {
        float4 af[8];
        uint4 bv[4];
#pragma unroll
        for (int it = 0; it < 8; it++) {
            int u = tid + it * 256;
            int row = u >> 4;           // 0..127
            int kq = (u & 15) * 4;      // 0..60 step 4
            af[it] = *(const float4*)(X + (m0 + row) * K + k0 + kq);
        }
#pragma unroll
        for (int it = 0; it < 4; it++) {
            int u = tid + it * 256;
            int row = u >> 3;
            int kq = (u & 7) * 8;
            bv[it] = *(const uint4*)(Bg + (n0 + row) * K + k0 + kq);
        }
        __syncthreads();
#pragma unroll
        for (int it = 0; it < 8; it++) {
            int u = tid + it * 256;
            int row = u >> 4;
            int kq = (u & 15) * 4;
            uint2 hw;
            hw.x = packh2(af[it].x, af[it].y);
            hw.y = packh2(af[it].z, af[it].w);
            *(uint2*)&sm[SA + row * TSG + kq] = hw;
        }
#pragma unroll
        for (int it = 0; it < 4; it++) {
            int u = tid + it * 256;
            int row = u >> 3;
            int kq = (u & 7) * 8;
            *(uint4*)&sm[SB + row * TSG + kq] = bv[it];
        }
        __syncthreads();

#pragma unroll
        for (int kc = 0; kc < 4; kc++) {
            int kk = kc * 16 + 2 * t4;
            uint32_t A[2][4];
#pragma unroll
            for (int mt = 0; mt < 2; mt++) {
                int r0 = mw + mt * 16 + g;
                int r1 = r0 + 8;
                A[mt][0] = *(const uint32_t*)&sm[SA + r0 * TSG + kk];
                A[mt][1] = *(const uint32_t*)&sm[SA + r1 * TSG + kk];
                A[mt][2] = *(const uint32_t*)&sm[SA + r0 * TSG + kk + 8];
                A[mt][3] = *(const uint32_t*)&sm[SA + r1 * TSG + kk + 8];
            }
#pragma unroll
            for (int nt = 0; nt < 8; nt++) {
                int nrow = nw + nt * 8 + g;
                uint32_t b0 = *(const uint32_t*)&sm[SB + nrow * TSG + kk];
                uint32_t b1 = *(const uint32_t*)&sm[SB + nrow * TSG + kk + 8];
                mmah(Cc[0][nt], A[0], b0, b1);
                mmah(Cc[1][nt], A[1], b0, b1);
            }
        }
    }

    // epilogue: write fp16
#pragma unroll
    for (int mt = 0; mt < 2; mt++) {
        int r0 = m0 + mw + mt * 16 + g;
        int r1 = r0 + 8;
#pragma unroll
        for (int nt = 0; nt < 8; nt++) {
            int col = n0 + nw + nt * 8 + 2 * t4;
            *(uint32_t*)(Gh + r0 * N + col) = packh2(Cc[mt][nt][0], Cc[mt][nt][1]);
            *(uint32_t*)(Gh + r1 * N + col) = packh2(Cc[mt][nt][2], Cc[mt][nt][3]);
        }
    }
}
#define CONV_SMEM_BYTES (2 * 128 * TSG * 2)

// ===================== gather taps -> f (fp16 in/out, ILP 8) ================
__global__ void gather_f_kernel(const float* __restrict__ cb0,
                                const float* __restrict__ cb1,
                                const float* __restrict__ cb2,
                                const float* __restrict__ cb3) {
    int t0 = blockIdx.x * 256 + threadIdx.x;   // 0..65535
#pragma unroll
    for (int q = 0; q < 8; q++) {
        int idx = t0 + q * 65536;
        int row = idx >> 8;        // (l,b): 0..2047
        int m = idx & 255;
        int l = row >> 4, b = row & 15;
        int br = m >> 6, c = m & 63;
        int k, pad, base;
        const float* cb;
        if (br == 0)      { k = 1; base = 0; cb = cb0; }
        else if (br == 1) { k = 3; base = 1; cb = cb1; }
        else if (br == 2) { k = 5; base = 4; cb = cb2; }
        else              { k = 7; base = 9; cb = cb3; }
        pad = (k - 1) >> 1;
        float sum = cb[c];
        for (int tt = 0; tt < k; tt++) {
            int l2 = l - pad + tt;
            if ((unsigned)l2 < (unsigned)LL)
                sum += __half2float(g_Gh[(l2 * BB + b) * GCOLS + (base + tt) * 64 + c]);
        }
        g_ff[idx] = __float2half_rn(lrelu(sum));
    }
}

// ===================== uv GEMM: full-K single-phase fp16 ====================
// uv(2048x128) = f(2048x256) @ Wuv[128][256]. Tile 64x64, whole K=256 staged.
#define TS2 264           // padded k-stride for K=256 (264*2B per row, 16B-mult)

__global__ void __launch_bounds__(256, 1)
gemm_uv_kernel(const __half* __restrict__ Ag,
               const __half* __restrict__ Bg,
               float* __restrict__ C) {
    const int N = 128, K = 256;
    constexpr int SA = 0;
    constexpr int SB = 64 * TS2;

    extern __shared__ __half sm[];
    int tid = threadIdx.x, w = tid >> 5, lane = tid & 31;
    int g = lane >> 2, t4 = lane & 3;
    int m0 = blockIdx.y * 64, n0 = blockIdx.x * 64;
    int mw = (w & 3) * 16;
    int nw = (w >> 2) * 32;

    // stage full K in one phase: 8 uint4 per thread per plane
    uint4 av[8], bv[8];
#pragma unroll
    for (int it = 0; it < 8; it++) {
        int u = tid + it * 256;
        int row = u >> 5;            // 0..63
        int kq = (u & 31) * 8;       // 0..248 step 8
        av[it] = *(const uint4*)(Ag + (m0 + row) * K + kq);
        bv[it] = *(const uint4*)(Bg + (n0 + row) * K + kq);
    }
#pragma unroll
    for (int it = 0; it < 8; it++) {
        int u = tid + it * 256;
        int row = u >> 5;
        int kq = (u & 31) * 8;
        *(uint4*)&sm[SA + row * TS2 + kq] = av[it];
        *(uint4*)&sm[SB + row * TS2 + kq] = bv[it];
    }
    __syncthreads();

    float Cc[4][4];
#pragma unroll
    for (int nt = 0; nt < 4; nt++)
#pragma unroll
        for (int q = 0; q < 4; q++) Cc[nt][q] = 0.f;

#pragma unroll
    for (int kc = 0; kc < 16; kc++) {
        int kk = kc * 16 + 2 * t4;
        uint32_t A[4];
        int r0 = mw + g, r1 = r0 + 8;
        A[0] = *(const uint32_t*)&sm[SA + r0 * TS2 + kk];
        A[1] = *(const uint32_t*)&sm[SA + r1 * TS2 + kk];
        A[2] = *(const uint32_t*)&sm[SA + r0 * TS2 + kk + 8];
        A[3] = *(const uint32_t*)&sm[SA + r1 * TS2 + kk + 8];
#pragma unroll
        for (int nt = 0; nt < 4; nt++) {
            int nrow = nw + nt * 8 + g;
            uint32_t b0 = *(const uint32_t*)&sm[SB + nrow * TS2 + kk];
            uint32_t b1 = *(const uint32_t*)&sm[SB + nrow * TS2 + kk + 8];
            mmah(Cc[nt], A, b0, b1);
        }
    }

    int r0 = m0 + mw + g, r1 = r0 + 8;
#pragma unroll
    for (int nt = 0; nt < 4; nt++) {
        int col = n0 + nw + nt * 8 + 2 * t4;
        *(float2*)(C + r0 * N + col) = make_float2(Cc[nt][0], Cc[nt][1]);
        *(float2*)(C + r1 * N + col) = make_float2(Cc[nt][2], Cc[nt][3]);
    }
}
#define UV_SMEM_BYTES (2 * 64 * TS2 * 2)

// ===================== pair kernel (round-12, unchanged) ====================
#define PV_STRIDE 132
#define P_W2   0
#define P_V    24576
#define P_U    58368
#define P_B    60416
#define P_RED  61440
#define P_SR   62464
#define P_TR   64512
#define PAIR_SMEM_BYTES 66560

__global__ void __launch_bounds__(128, 2)
pair_mma_kernel(const float* __restrict__ uv,
                const float* __restrict__ mw1, const float* __restrict__ mw2,
                const float* __restrict__ mw3,
                const float* __restrict__ mb0, const float* __restrict__ mb1,
                const float* __restrict__ mb2, const float* __restrict__ mb3,
                const float* __restrict__ lw0, const float* __restrict__ lb0,
                const float* __restrict__ lw1, const float* __restrict__ lb1,
                float* __restrict__ out) {
    extern __shared__ char smp[];
    int tid = threadIdx.x, w = tid >> 5, lane = tid & 31;
    int g = lane >> 2, t4 = lane & 3;
    int b = blockIdx.y, j0 = blockIdx.x * 8;

    // ---- stage weights as packed uint2 fragments (single fp16) ----
    {
        uint2* W2 = (uint2*)(smp + P_W2);
        for (int e = tid; e < 3072; e += 128) {
            int t4i = e & 3;
            int n = (e >> 2) & 63;
            int kc = (e >> 8) & 3;
            int l = e >> 10;
            const float* wsrc = (l == 0) ? mw1 : (l == 1) ? mw2 : mw3;
            int k0 = kc * 16 + 2 * t4i;
            float2 v01 = *(const float2*)(wsrc + n * 64 + k0);
            float2 v89 = *(const float2*)(wsrc + n * 64 + k0 + 8);
            uint2 pk;
            pk.x = packh2(v01.x, v01.y);
            pk.y = packh2(v89.x, v89.y);
            W2[e] = pk;
        }
    }
    // ---- stage V[k][i] (f32, stride 132) ----
    {
        float* V = (float*)(smp + P_V);
        const float* vp = uv + (tid * BB + b) * 128 + 64;
#pragma unroll
        for (int q = 0; q < 16; q++) {
            float4 v4 = *(const float4*)(vp + q * 4);
            V[(q * 4 + 0) * PV_STRIDE + tid] = v4.x;
            V[(q * 4 + 1) * PV_STRIDE + tid] = v4.y;
            V[(q * 4 + 2) * PV_STRIDE + tid] = v4.z;
            V[(q * 4 + 3) * PV_STRIDE + tid] = v4.w;
        }
    }
    if (tid < 64) {
        float* U = (float*)(smp + P_U);
#pragma unroll
        for (int jt = 0; jt < 8; jt++)
            U[jt * 64 + tid] = uv[((j0 + jt) * BB + b) * 128 + tid];
        float* Bs = (float*)(smp + P_B);
        Bs[tid] = mb0[tid];
        Bs[64 + tid] = mb1[tid];
        Bs[128 + tid] = mb2[tid];
        Bs[192 + tid] = mb3[tid];
    }
    __syncthreads();

    const float* V = (const float*)(smp + P_V);
    const float* U = (const float*)(smp + P_U);
    const float* BIAS = (const float*)(smp + P_B);
    const uint2* W2 = (const uint2*)(smp + P_W2);
    float* RED = (float*)(smp + P_RED);
    float* SR = (float*)(smp + P_SR);

    for (int jt = 0; jt < 8; jt++) {
        uint32_t A[2][4][4];

        // ---- layer-1 A fragments: x = lrelu(u + v + b0), single fp16 ----
#pragma unroll
        for (int mt = 0; mt < 2; mt++) {
            int r0 = w * 32 + mt * 16 + g;
            int r1 = r0 + 8;
#pragma unroll
            for (int kc = 0; kc < 4; kc++) {
                int k0 = kc * 16 + 2 * t4;
                float ub0 = U[jt * 64 + k0]     + BIAS[k0];
                float ub1 = U[jt * 64 + k0 + 1] + BIAS[k0 + 1];
                float ub8 = U[jt * 64 + k0 + 8] + BIAS[k0 + 8];
                float ub9 = U[jt * 64 + k0 + 9] + BIAS[k0 + 9];
                float x00 = lrelu(ub0 + V[k0 * PV_STRIDE + r0]);
                float x01 = lrelu(ub1 + V[(k0 + 1) * PV_STRIDE + r0]);
                float x10 = lrelu(ub0 + V[k0 * PV_STRIDE + r1]);
                float x11 = lrelu(ub1 + V[(k0 + 1) * PV_STRIDE + r1]);
                float x08 = lrelu(ub8 + V[(k0 + 8) * PV_STRIDE + r0]);
                float x09 = lrelu(ub9 + V[(k0 + 9) * PV_STRIDE + r0]);
                float x18 = lrelu(ub8 + V[(k0 + 8) * PV_STRIDE + r1]);
                float x19 = lrelu(ub9 + V[(k0 + 9) * PV_STRIDE + r1]);
                A[mt][kc][0] = packh2(x00, x01);
                A[mt][kc][1] = packh2(x10, x11);
                A[mt][kc][2] = packh2(x08, x09);
                A[mt][kc][3] = packh2(x18, x19);
            }
        }

        // ---- 3 chained MMA layers (single-term: A*W) ----
        float Cc[2][8][4];
#pragma unroll
        for (int l = 0; l < 3; l++) {
#pragma unroll
            for (int mt = 0; mt < 2; mt++)
#pragma unroll
                for (int nt = 0; nt < 8; nt++)
#pragma unroll
                    for (int q = 0; q < 4; q++) Cc[mt][nt][q] = 0.f;

#pragma unroll
            for (int kc = 0; kc < 4; kc++) {
#pragma unroll
                for (int nt = 0; nt < 8; nt++) {
                    uint2 wq = W2[((l * 4 + kc) * 64 + nt * 8 + g) * 4 + t4];
                    mmah(Cc[0][nt], A[0][kc], wq.x, wq.y);
                    mmah(Cc[1][nt], A[1][kc], wq.x, wq.y);
                }
            }

            if (l < 2) {
                const float* bl = BIAS + 64 * (l + 1);
#pragma unroll
                for (int nt = 0; nt < 8; nt++) {
                    int col = nt * 8 + 2 * t4;
                    float bx = bl[col], by = bl[col + 1];
                    int kc2 = nt >> 1, ri = (nt & 1) * 2;
#pragma unroll
                    for (int mt = 0; mt < 2; mt++) {
                        float h0 = lrelu(Cc[mt][nt][0] + bx);
                        float h1 = lrelu(Cc[mt][nt][1] + by);
                        float h2 = lrelu(Cc[mt][nt][2] + bx);
                        float h3 = lrelu(Cc[mt][nt][3] + by);
                        A[mt][kc2][ri]     = packh2(h0, h1);
                        A[mt][kc2][ri + 1] = packh2(h2, h3);
                    }
                }
            }
        }

        // ---- final: bias + lrelu, reduce over i ----
        {
            const float* bl = BIAS + 192;
#pragma unroll
            for (int nt = 0; nt < 8; nt++) {
                int col = nt * 8 + 2 * t4;
                float bx = bl[col], by = bl[col + 1];
                float s0 = lrelu(Cc[0][nt][0] + bx) + lrelu(Cc[0][nt][2] + bx) +
                           lrelu(Cc[1][nt][0] + bx) + lrelu(Cc[1][nt][2] + bx);
                float s1 = lrelu(Cc[0][nt][1] + by) + lrelu(Cc[0][nt][3] + by) +
                           lrelu(Cc[1][nt][1] + by) + lrelu(Cc[1][nt][3] + by);
                s0 += __shfl_xor_sync(0xffffffffu, s0, 4);
                s0 += __shfl_xor_sync(0xffffffffu, s0, 8);
                s0 += __shfl_xor_sync(0xffffffffu, s0, 16);
                s1 += __shfl_xor_sync(0xffffffffu, s1, 4);
                s1 += __shfl_xor_sync(0xffffffffu, s1, 8);
                s1 += __shfl_xor_sync(0xffffffffu, s1, 16);
                if (lane < 4) {
                    RED[w * 64 + col] = s0;
                    RED[w * 64 + col + 1] = s1;
                }
            }
        }
        __syncthreads();
        if (tid < 64) {
            float s = RED[tid] + RED[64 + tid] + RED[128 + tid] + RED[192 + tid];
            SR[jt * 64 + tid] = s;
        }
        __syncthreads();
    }

    // ---- fused head: t = lrelu(s@lw0.T+lb0); out = lrelu(t@lw1.T+lb1) ----
    float* TR = (float*)(smp + P_TR);
#pragma unroll
    for (int q = 0; q < 4; q++) {
        int idx = tid + 128 * q;
        int jt = idx >> 6, o = idx & 63;
        const float* wr = lw0 + o * 64;
        float acc = lb0[o];
#pragma unroll
        for (int c = 0; c < 64; c += 4) {
            float4 w4 = *(const float4*)(wr + c);
            acc += SR[jt * 64 + c] * w4.x + SR[jt * 64 + c + 1] * w4.y +
                   SR[jt * 64 + c + 2] * w4.z + SR[jt * 64 + c + 3] * w4.w;
        }
        TR[idx] = lrelu(acc);
    }
    __syncthreads();
#pragma unroll
    for (int q = 0; q < 16; q++) {
        int idx = tid + 128 * q;
        int jt = idx >> 8, o = idx & 255;
        const float* wr = lw1 + o * 64;
        float acc = lb1[o];
#pragma unroll
        for (int c = 0; c < 64; c += 4) {
            float4 w4 = *(const float4*)(wr + c);
            acc += TR[jt * 64 + c] * w4.x + TR[jt * 64 + c + 1] * w4.y +
                   TR[jt * 64 + c + 2] * w4.z + TR[jt * 64 + c + 3] * w4.w;
        }
        out[((j0 + jt) * BB + b) * 256 + o] = lrelu(acc);
    }
}

// ===================== host launch ==========================================
extern "C" void kernel_launch(void* const* d_in, const int* in_sizes, int n_in,
                              void* d_out, int out_size) {
    const float* x   = (const float*)d_in[0];
    const float* cw0 = (const float*)d_in[1];
    const float* cb0 = (const float*)d_in[2];
    const float* cw1 = (const float*)d_in[3];
    const float* cb1 = (const float*)d_in[4];
    const float* cw2 = (const float*)d_in[5];
    const float* cb2 = (const float*)d_in[6];
    const float* cw3 = (const float*)d_in[7];
    const float* cb3 = (const float*)d_in[8];
    const float* mw0 = (const float*)d_in[9];
    const float* mb0 = (const float*)d_in[10];
    const float* mw1 = (const float*)d_in[11];
    const float* mb1 = (const float*)d_in[12];
    const float* mw2 = (const float*)d_in[13];
    const float* mb2 = (const float*)d_in[14];
    const float* mw3 = (const float*)d_in[15];
    const float* mb3 = (const float*)d_in[16];
    const float* lw0 = (const float*)d_in[17];
    const float* lb0 = (const float*)d_in[18];
    const float* lw1 = (const float*)d_in[19];
    const float* lb1 = (const float*)d_in[20];
    float* out = (float*)d_out;

    float* uvb;
    __half *Gh, *ff, *Wrh, *Wuvh;
    cudaGetSymbolAddress((void**)&Gh, g_Gh);
    cudaGetSymbolAddress((void**)&uvb, g_uv);
    cudaGetSymbolAddress((void**)&ff, g_ff);
    cudaGetSymbolAddress((void**)&Wrh, g_Wrh);
    cudaGetSymbolAddress((void**)&Wuvh, g_Wuvh);

    // 1) prep (weights only)
    prep_kernel<<<(NW + NU + 255) / 256, 256>>>(cw0, cw1, cw2, cw3, mw0);

    // 2) conv as GEMM: G = x @ Wr (x cvt inline, G fp16)
    cudaFuncSetAttribute(gemm_conv_kernel,
                         cudaFuncAttributeMaxDynamicSharedMemorySize,
                         CONV_SMEM_BYTES);
    gemm_conv_kernel<<<dim3(GCOLS / 128, ROWS / 128), 256, CONV_SMEM_BYTES>>>(
        x, Wrh, Gh);

    // 3) gather taps -> f (fp16)
    gather_f_kernel<<<256, 256>>>(cb0, cb1, cb2, cb3);

    // 4) uv = f @ Wuv (full-K single-phase, 64x64 tiles)
    cudaFuncSetAttribute(gemm_uv_kernel,
                         cudaFuncAttributeMaxDynamicSharedMemorySize,
                         UV_SMEM_BYTES);
    gemm_uv_kernel<<<dim3(2, ROWS / 64), 256, UV_SMEM_BYTES>>>(
        ff, Wuvh, uvb);

    // 5) pair stage + fused head (pure fp16, round-6 structure)
    cudaFuncSetAttribute(pair_mma_kernel,
                         cudaFuncAttributeMaxDynamicSharedMemorySize,
                         PAIR_SMEM_BYTES);
    pair_mma_kernel<<<dim3(16, 16), 128, PAIR_SMEM_BYTES>>>(
        uvb, mw1, mw2, mw3, mb0, mb1, mb2, mb3,
        lw0, lb0, lw1, lb1, out);
}